// round 6
// baseline (speedup 1.0000x reference)
#include <cuda_runtime.h>
#include <cuda_bf16.h>

#define B_   2
#define S_   2048
#define D_   1024
#define H_   16
#define DK_  64
#define BS_  (B_*S_)            // 4096
#define NBH_ (B_*H_)            // 32

// ---------------- device scratch (no allocations allowed) -------------------
__device__ __nv_bfloat16 g_xh[BS_ * D_],  g_xl[BS_ * D_];
__device__ __nv_bfloat16 g_w3h[3 * D_ * D_], g_w3l[3 * D_ * D_];
__device__ __nv_bfloat16 g_woh[D_ * D_], g_wol[D_ * D_];
__device__ __nv_bfloat16 g_qh[NBH_ * S_ * DK_], g_ql[NBH_ * S_ * DK_];
__device__ __nv_bfloat16 g_kh[NBH_ * S_ * DK_], g_kl[NBH_ * S_ * DK_];
__device__ __nv_bfloat16 g_vth[NBH_ * DK_ * S_], g_vtl[NBH_ * DK_ * S_]; // V^T [bh][d][s]
__device__ __nv_bfloat16 g_ch[BS_ * D_], g_cl[BS_ * D_];
__device__ float g_rsum_part[64][NBH_ * S_];              // deterministic partials
__device__ float g_inv[NBH_ * S_];                        // 1/rowsum
__device__ float g_ctxp[2 * BS_ * D_];                    // split-K ctx partials
__device__ float g_attn_fb[(size_t)NBH_ * S_ * S_];       // fallback

// ---------------- smem layout for plain GEMMs (per stage) --------------------
#define OFF_AH 0
#define OFF_AL 16384
#define OFF_BH 32768
#define OFF_BL 40960
#define STAGE_BYTES 49152

// ---------------- smem layout for pv_fused ------------------------------------
#define PV_Q_H 0
#define PV_Q_L 16384
#define PV_K_H 32768
#define PV_K_L 40960
#define PV_P_H 49152
#define PV_P_L 65536
#define PV_V_H 81920
#define PV_V_L 90112
#define PV_SMEM 98304

// ---------------- helpers ----------------------------------------------------
__device__ __forceinline__ unsigned smem_u32(const void* p) {
    return (unsigned)__cvta_generic_to_shared(p);
}
__device__ __forceinline__ void ldsm4(unsigned r[4], unsigned addr) {
    asm volatile("ldmatrix.sync.aligned.m8n8.x4.shared.b16 {%0,%1,%2,%3}, [%4];\n"
                 : "=r"(r[0]), "=r"(r[1]), "=r"(r[2]), "=r"(r[3]) : "r"(addr));
}
__device__ __forceinline__ void mma16816(float (&d)[4], const unsigned a[4],
                                         unsigned b0, unsigned b1) {
    asm volatile(
        "mma.sync.aligned.m16n8k16.row.col.f32.bf16.bf16.f32 "
        "{%0,%1,%2,%3}, {%4,%5,%6,%7}, {%8,%9}, {%0,%1,%2,%3};\n"
        : "+f"(d[0]), "+f"(d[1]), "+f"(d[2]), "+f"(d[3])
        : "r"(a[0]), "r"(a[1]), "r"(a[2]), "r"(a[3]), "r"(b0), "r"(b1));
}
__device__ __forceinline__ void split2(float x, float y, unsigned &h, unsigned &l) {
    __nv_bfloat162 hv = __floats2bfloat162_rn(x, y);
    float rx = x - __low2float(hv);
    float ry = y - __high2float(hv);
    __nv_bfloat162 lv = __floats2bfloat162_rn(rx, ry);
    h = *reinterpret_cast<unsigned*>(&hv);
    l = *reinterpret_cast<unsigned*>(&lv);
}
__device__ __forceinline__ unsigned swz(int row, int kb) {
    return (unsigned)(row * 128 + (kb ^ ((row & 7) << 4)));
}
__device__ __forceinline__ void cp16(unsigned dst, const void* src) {
    asm volatile("cp.async.cg.shared.global [%0], [%1], 16;\n" :: "r"(dst), "l"(src));
}
#define CP_COMMIT asm volatile("cp.async.commit_group;\n" ::: "memory")
#define CP_WAIT1  asm volatile("cp.async.wait_group 1;\n" ::: "memory")
#define CP_WAIT0  asm volatile("cp.async.wait_group 0;\n" ::: "memory")

// ---------------- cp.async tile staging ---------------------------------------
__device__ __forceinline__ void cpA_tile(unsigned AH, unsigned AL,
    const __nv_bfloat16* __restrict__ Ah, const __nv_bfloat16* __restrict__ Al,
    int ld, int m0, int k0, int tid)
{
#pragma unroll
    for (int j = 0; j < 4; j++) {
        int id = tid + j * 256, row = id >> 3, c = id & 7;
        size_t g = (size_t)(m0 + row) * ld + k0 + c * 8;
        unsigned o = swz(row, c * 16);
        cp16(AH + o, Ah + g);
        cp16(AL + o, Al + g);
    }
}
__device__ __forceinline__ void cpB_tile(unsigned BH, unsigned BL,
    const __nv_bfloat16* __restrict__ Bh, const __nv_bfloat16* __restrict__ Bl,
    int ld, int n0, int k0, int tid)
{
#pragma unroll
    for (int j = 0; j < 2; j++) {
        int id = tid + j * 256, row = id >> 3, c = id & 7;
        size_t g = (size_t)(n0 + row) * ld + k0 + c * 8;
        unsigned o = swz(row, c * 16);
        cp16(BH + o, Bh + g);
        cp16(BL + o, Bl + g);
    }
}

// ---------------- core compute over one BK=64 stage ---------------------------
// A tile at aBase (hi) / aBase+16384 (lo), 128 rows.
// B tile at bBase (hi) / bBase+8192  (lo), 64 rows.
__device__ __forceinline__ void compute_stage(unsigned aBase, unsigned bBase,
                                              int wm, int wn, int lane,
                                              float acc[2][4][4])
{
    const int arow0 = wm * 32 + (lane & 15);
    const int akh   = ((lane >> 4) & 1) * 16;
    const int brow0 = wn * 32 + ((lane >> 4) & 1) * 8 + (lane & 7);
    const int bkh   = ((lane >> 3) & 1) * 16;
#pragma unroll
    for (int ks = 0; ks < 4; ks++) {
        unsigned ah[2][4], al[2][4], bh[2][4], bl[2][4];
#pragma unroll
        for (int mt = 0; mt < 2; mt++) {
            unsigned off = swz(arow0 + mt * 16, ks * 32 + akh);
            ldsm4(ah[mt], aBase + off);
            ldsm4(al[mt], aBase + 16384 + off);
        }
#pragma unroll
        for (int p = 0; p < 2; p++) {
            unsigned off = swz(brow0 + p * 16, ks * 32 + bkh);
            ldsm4(bh[p], bBase + off);
            ldsm4(bl[p], bBase + 8192 + off);
        }
#pragma unroll
        for (int mt = 0; mt < 2; mt++)
#pragma unroll
            for (int nt = 0; nt < 4; nt++) {
                unsigned b0h = bh[nt >> 1][(nt & 1) * 2], b1h = bh[nt >> 1][(nt & 1) * 2 + 1];
                unsigned b0l = bl[nt >> 1][(nt & 1) * 2], b1l = bl[nt >> 1][(nt & 1) * 2 + 1];
                mma16816(acc[mt][nt], ah[mt], b0h, b1h);
                mma16816(acc[mt][nt], ah[mt], b0l, b1l);
                mma16816(acc[mt][nt], al[mt], b0h, b1h);
            }
    }
}

// ---------------- prep: fp32 -> hi/lo bf16 splits ------------------------------
__global__ void prep_kernel(const float* __restrict__ x,
                            const float* __restrict__ wq,
                            const float* __restrict__ wk,
                            const float* __restrict__ wv,
                            const float* __restrict__ wo)
{
    const int bid = blockIdx.x, tid = threadIdx.x;
    const float* src;
    __nv_bfloat16 *hi, *lo;
    int base;
    if (bid < 8192)        { src = x;  hi = g_xh;            lo = g_xl;            base = 0; }
    else if (bid < 10240)  { src = wq; hi = g_w3h;           lo = g_w3l;           base = 8192; }
    else if (bid < 12288)  { src = wk; hi = g_w3h + D_*D_;   lo = g_w3l + D_*D_;   base = 10240; }
    else if (bid < 14336)  { src = wv; hi = g_w3h + 2*D_*D_; lo = g_w3l + 2*D_*D_; base = 12288; }
    else                   { src = wo; hi = g_woh;           lo = g_wol;           base = 14336; }
    int i = ((bid - base) * 256 + tid) * 2;
    unsigned h, l;
    split2(src[i], src[i + 1], h, l);
    *reinterpret_cast<unsigned*>(hi + i) = h;
    *reinterpret_cast<unsigned*>(lo + i) = l;
}

// =============================================================================
// Kernel 1: fused QKV projection; Q pre-scaled by 1/8; V stored transposed
// =============================================================================
__global__ __launch_bounds__(256, 2) void qkv_gemm(const float* __restrict__ bq,
                                                   const float* __restrict__ bk,
                                                   const float* __restrict__ bv)
{
    extern __shared__ char sm[];
    const unsigned sb = smem_u32(sm);
    const int m0 = blockIdx.y * 128, n0 = blockIdx.x * 64;
    const int tid = threadIdx.x, lane = tid & 31, wid = tid >> 5;
    const int wm = wid >> 1, wn = wid & 1;
    float acc[2][4][4] = {};

    cpA_tile(sb + OFF_AH, sb + OFF_AL, g_xh, g_xl, D_, m0, 0, tid);
    cpB_tile(sb + OFF_BH, sb + OFF_BL, g_w3h, g_w3l, D_, n0, 0, tid);
    CP_COMMIT;
    for (int it = 0; it < 16; it++) {
        const unsigned cb = sb + (it & 1) * STAGE_BYTES;
        if (it + 1 < 16) {
            const unsigned nb = sb + ((it + 1) & 1) * STAGE_BYTES;
            cpA_tile(nb + OFF_AH, nb + OFF_AL, g_xh, g_xl, D_, m0, (it + 1) * 64, tid);
            cpB_tile(nb + OFF_BH, nb + OFF_BL, g_w3h, g_w3l, D_, n0, (it + 1) * 64, tid);
            CP_COMMIT;
            CP_WAIT1;
        } else { CP_WAIT0; }
        __syncthreads();
        compute_stage(cb + OFF_AH, cb + OFF_BH, wm, wn, lane, acc);
        __syncthreads();
    }

    const int reg = n0 >> 10;                 // 0=Q,1=K,2=V
    const int h   = (n0 & 1023) >> 6;
    const float* bp = (reg == 0) ? bq : (reg == 1) ? bk : bv;
    __nv_bfloat16* dH = (reg == 0) ? g_qh : g_kh;
    __nv_bfloat16* dL = (reg == 0) ? g_ql : g_kl;
    const float scale = (reg == 0) ? 0.125f : 1.0f;
    const int tm0 = m0 + wm * 32, tn0 = n0 + wn * 32;

#pragma unroll
    for (int mt = 0; mt < 2; mt++)
#pragma unroll
        for (int nt = 0; nt < 4; nt++) {
            const int c  = tn0 + nt * 8 + 2 * (lane & 3);
            const int d  = c & 63;
            const float bias0 = bp[c & 1023], bias1 = bp[(c & 1023) + 1];
#pragma unroll
            for (int half = 0; half < 2; half++) {
                const int m = tm0 + mt * 16 + (lane >> 2) + half * 8;
                const float v0 = (acc[mt][nt][half * 2]     + bias0) * scale;
                const float v1 = (acc[mt][nt][half * 2 + 1] + bias1) * scale;
                const int b = m >> 11, s = m & 2047;
                const size_t bh = (size_t)(b * H_ + h);
                unsigned hh, ll;
                split2(v0, v1, hh, ll);
                if (reg < 2) {
                    size_t idx = (bh * S_ + s) * DK_ + d;
                    *reinterpret_cast<unsigned*>(dH + idx) = hh;
                    *reinterpret_cast<unsigned*>(dL + idx) = ll;
                } else {
                    size_t i0 = (bh * DK_ + d) * S_ + s;
                    __nv_bfloat162 hv = *reinterpret_cast<__nv_bfloat162*>(&hh);
                    __nv_bfloat162 lv = *reinterpret_cast<__nv_bfloat162*>(&ll);
                    g_vth[i0]      = __low2bfloat16(hv);
                    g_vtl[i0]      = __low2bfloat16(lv);
                    g_vth[i0 + S_] = __high2bfloat16(hv);
                    g_vtl[i0 + S_] = __high2bfloat16(lv);
                }
            }
        }
}

// =============================================================================
// Kernel 2: scores_lite — exp(QK^T/8) rowsum partials ONLY (no P store)
// =============================================================================
__global__ __launch_bounds__(256) void scores_lite()
{
    extern __shared__ char sm[];
    const unsigned sb = smem_u32(sm);
    const int bh = blockIdx.z;
    const int m0 = blockIdx.y * 128, n0 = blockIdx.x * 64;
    const int tid = threadIdx.x, lane = tid & 31, wid = tid >> 5;
    const int wm = wid >> 1, wn = wid & 1;

    const __nv_bfloat16* Ah = g_qh + (size_t)bh * S_ * DK_;
    const __nv_bfloat16* Al = g_ql + (size_t)bh * S_ * DK_;
    const __nv_bfloat16* Bh = g_kh + (size_t)bh * S_ * DK_;
    const __nv_bfloat16* Bl = g_kl + (size_t)bh * S_ * DK_;

    float acc[2][4][4] = {};
    cpA_tile(sb + OFF_AH, sb + OFF_AL, Ah, Al, DK_, m0, 0, tid);
    cpB_tile(sb + OFF_BH, sb + OFF_BL, Bh, Bl, DK_, n0, 0, tid);
    CP_COMMIT;
    CP_WAIT0;
    __syncthreads();
    compute_stage(sb + OFF_AH, sb + OFF_BH, wm, wn, lane, acc);

    const int tm0 = m0 + wm * 32;
    float rpart[2][2] = {};
#pragma unroll
    for (int mt = 0; mt < 2; mt++)
#pragma unroll
        for (int nt = 0; nt < 4; nt++)
#pragma unroll
            for (int half = 0; half < 2; half++) {
                rpart[mt][half] += __expf(acc[mt][nt][half * 2])
                                 + __expf(acc[mt][nt][half * 2 + 1]);
            }

    const int slot = blockIdx.x * 2 + wn;
#pragma unroll
    for (int mt = 0; mt < 2; mt++)
#pragma unroll
        for (int half = 0; half < 2; half++) {
            float v = rpart[mt][half];
            v += __shfl_xor_sync(0xffffffffu, v, 1);
            v += __shfl_xor_sync(0xffffffffu, v, 2);
            if ((lane & 3) == 0) {
                const int m = tm0 + mt * 16 + (lane >> 2) + half * 8;
                g_rsum_part[slot][(size_t)bh * S_ + m] = v;
            }
        }
}

// ---------------- inv_kernel: 1/rowsum from 64 partials ------------------------
__global__ void inv_kernel()
{
    const int r = blockIdx.x * 256 + threadIdx.x;   // 65536 rows
    float s = 0.f;
#pragma unroll
    for (int p = 0; p < 64; p++) s += g_rsum_part[p][r];
    g_inv[r] = 1.0f / s;
}

// =============================================================================
// Kernel 3: pv_fused — recompute S, exp, write normalized attn, P·V on the fly
// grid (kz=2, mtile=16, bh=32); each block covers k-range 1024 in 16 subtiles
// =============================================================================
__global__ __launch_bounds__(256, 2) void pv_fused(float* __restrict__ attn_arg)
{
    extern __shared__ char sm[];
    __shared__ float s_inv[128];
    const unsigned sb = smem_u32(sm);
    float* attn = attn_arg ? attn_arg : g_attn_fb;
    const int kz = blockIdx.x, bh = blockIdx.z;
    const int m0 = blockIdx.y * 128;
    const int tid = threadIdx.x, lane = tid & 31, wid = tid >> 5;
    const int wm = wid >> 1, wn = wid & 1;

    if (tid < 128) s_inv[tid] = g_inv[(size_t)bh * S_ + m0 + tid];

    const __nv_bfloat16* Qh = g_qh + (size_t)bh * S_ * DK_;
    const __nv_bfloat16* Ql = g_ql + (size_t)bh * S_ * DK_;
    const __nv_bfloat16* Kh = g_kh + (size_t)bh * S_ * DK_;
    const __nv_bfloat16* Kl = g_kl + (size_t)bh * S_ * DK_;
    const __nv_bfloat16* Vh = g_vth + (size_t)bh * DK_ * S_;
    const __nv_bfloat16* Vl = g_vtl + (size_t)bh * DK_ * S_;
    float* Aout = attn + (size_t)bh * S_ * S_;

    // persistent Q tile (128 x 64 hi/lo)
    cpA_tile(sb + PV_Q_H, sb + PV_Q_L, Qh, Ql, DK_, m0, 0, tid);
    CP_COMMIT;

    float ctx[2][4][4] = {};

    for (int kt = 0; kt < 16; kt++) {
        const int n0g = kz * 1024 + kt * 64;

        // K subtile (64 x 64) and V subtile (64 d-rows x 64 s-cols)
        cpB_tile(sb + PV_K_H, sb + PV_K_L, Kh, Kl, DK_, n0g, 0, tid);
        cpB_tile(sb + PV_V_H, sb + PV_V_L, Vh, Vl, S_, 0, n0g, tid);
        CP_COMMIT;
        CP_WAIT0;
        __syncthreads();   // K/V ready; prev iter's PV reads of P/K/V complete

        // S = (Q/8) K^T for this 128x64 subtile
        float sacc[2][4][4] = {};
        compute_stage(sb + PV_Q_H, sb + PV_K_H, wm, wn, lane, sacc);

        // exp -> smem P tile (hi/lo) + normalized fp32 attn to gmem
#pragma unroll
        for (int mt = 0; mt < 2; mt++)
#pragma unroll
            for (int nt = 0; nt < 4; nt++)
#pragma unroll
                for (int half = 0; half < 2; half++) {
                    const int row  = wm * 32 + mt * 16 + (lane >> 2) + half * 8;
                    const int coln = wn * 32 + nt * 8 + 2 * (lane & 3);
                    const float e0 = __expf(sacc[mt][nt][half * 2]);
                    const float e1 = __expf(sacc[mt][nt][half * 2 + 1]);
                    unsigned hh, ll;
                    split2(e0, e1, hh, ll);
                    const unsigned bo  = (unsigned)(coln * 2);
                    const unsigned swo = (unsigned)(row * 128)
                                       + (((bo & 0xFFF0u) ^ (unsigned)((row & 7) << 4)))
                                       + (bo & 15u);
                    asm volatile("st.shared.b32 [%0], %1;" :: "r"(sb + PV_P_H + swo), "r"(hh));
                    asm volatile("st.shared.b32 [%0], %1;" :: "r"(sb + PV_P_L + swo), "r"(ll));
                    const float inv = s_inv[row];
                    float2 o = { e0 * inv, e1 * inv };
                    *reinterpret_cast<float2*>(&Aout[(size_t)(m0 + row) * S_ + n0g + coln]) = o;
                }
        __syncthreads();   // P tile visible to all warps

        // ctx += P · V  (A = P tile, B = V tile)
        compute_stage(sb + PV_P_H, sb + PV_V_H, wm, wn, lane, ctx);
        __syncthreads();   // all warps done with P/K/V before next overwrite
    }

    // epilogue: fp32 partial ctx scaled by inv -> g_ctxp[kz]
    const int b = bh >> 4, h = bh & 15;
    float* dst = g_ctxp + (size_t)kz * BS_ * D_;
#pragma unroll
    for (int mt = 0; mt < 2; mt++)
#pragma unroll
        for (int nt = 0; nt < 4; nt++) {
            const int c = wn * 32 + nt * 8 + 2 * (lane & 3);
#pragma unroll
            for (int half = 0; half < 2; half++) {
                const int rowl = wm * 32 + mt * 16 + (lane >> 2) + half * 8;
                const float inv = s_inv[rowl];
                const int s = m0 + rowl;
                float2 v = { ctx[mt][nt][half * 2] * inv,
                             ctx[mt][nt][half * 2 + 1] * inv };
                *reinterpret_cast<float2*>(&dst[(size_t)(b * S_ + s) * D_ + h * DK_ + c]) = v;
            }
        }
}

// ---------------- ctx reduce: sum 2 partials -> hi/lo bf16 ---------------------
__global__ void ctx_reduce()
{
    const size_t i = ((size_t)blockIdx.x * 256 + threadIdx.x) * 2;
    float2 a = *reinterpret_cast<const float2*>(&g_ctxp[i]);
    float2 b = *reinterpret_cast<const float2*>(&g_ctxp[(size_t)BS_ * D_ + i]);
    unsigned hh, ll;
    split2(a.x + b.x, a.y + b.y, hh, ll);
    *reinterpret_cast<unsigned*>(g_ch + i) = hh;
    *reinterpret_cast<unsigned*>(g_cl + i) = ll;
}

// =============================================================================
// Kernel 4: out = ctx @ Wo^T + bo
// =============================================================================
__global__ __launch_bounds__(256, 2) void oproj_gemm(const float* __restrict__ bo,
                                                     float* __restrict__ out)
{
    extern __shared__ char sm[];
    const unsigned sb = smem_u32(sm);
    const int m0 = blockIdx.y * 128, n0 = blockIdx.x * 64;
    const int tid = threadIdx.x, lane = tid & 31, wid = tid >> 5;
    const int wm = wid >> 1, wn = wid & 1;
    float acc[2][4][4] = {};

    cpA_tile(sb + OFF_AH, sb + OFF_AL, g_ch, g_cl, D_, m0, 0, tid);
    cpB_tile(sb + OFF_BH, sb + OFF_BL, g_woh, g_wol, D_, n0, 0, tid);
    CP_COMMIT;
    for (int it = 0; it < 16; it++) {
        const unsigned cb = sb + (it & 1) * STAGE_BYTES;
        if (it + 1 < 16) {
            const unsigned nb = sb + ((it + 1) & 1) * STAGE_BYTES;
            cpA_tile(nb + OFF_AH, nb + OFF_AL, g_ch, g_cl, D_, m0, (it + 1) * 64, tid);
            cpB_tile(nb + OFF_BH, nb + OFF_BL, g_woh, g_wol, D_, n0, (it + 1) * 64, tid);
            CP_COMMIT;
            CP_WAIT1;
        } else { CP_WAIT0; }
        __syncthreads();
        compute_stage(cb + OFF_AH, cb + OFF_BH, wm, wn, lane, acc);
        __syncthreads();
    }

    const int tm0 = m0 + wm * 32, tn0 = n0 + wn * 32;
#pragma unroll
    for (int mt = 0; mt < 2; mt++)
#pragma unroll
        for (int nt = 0; nt < 4; nt++) {
            const int c = tn0 + nt * 8 + 2 * (lane & 3);
            const float b0 = bo[c], b1 = bo[c + 1];
#pragma unroll
            for (int half = 0; half < 2; half++) {
                const int m = tm0 + mt * 16 + (lane >> 2) + half * 8;
                float2 v = { acc[mt][nt][half * 2] + b0,
                             acc[mt][nt][half * 2 + 1] + b1 };
                *reinterpret_cast<float2*>(out + (size_t)m * D_ + c) = v;
            }
        }
}

// =============================================================================
extern "C" void kernel_launch(void* const* d_in, const int* in_sizes, int n_in,
                              void* d_out, int out_size)
{
    const float* x  = (const float*)d_in[0];
    const float* wq = (const float*)d_in[1];
    const float* bq = (const float*)d_in[2];
    const float* wk = (const float*)d_in[3];
    const float* bk = (const float*)d_in[4];
    const float* wv = (const float*)d_in[5];
    const float* bv = (const float*)d_in[6];
    const float* wo = (const float*)d_in[7];
    const float* bo = (const float*)d_in[8];

    float* out = (float*)d_out;
    const long long OUT_E  = (long long)BS_ * D_;
    const long long ATTN_E = (long long)NBH_ * S_ * S_;
    float* attn = ((long long)out_size >= OUT_E + ATTN_E) ? (out + OUT_E) : nullptr;

    static bool attr_done = false;
    if (!attr_done) {
        cudaFuncSetAttribute(qkv_gemm,    cudaFuncAttributeMaxDynamicSharedMemorySize, 2 * STAGE_BYTES);
        cudaFuncSetAttribute(pv_fused,    cudaFuncAttributeMaxDynamicSharedMemorySize, PV_SMEM);
        cudaFuncSetAttribute(oproj_gemm,  cudaFuncAttributeMaxDynamicSharedMemorySize, 2 * STAGE_BYTES);
        cudaFuncSetAttribute(scores_lite, cudaFuncAttributeMaxDynamicSharedMemorySize, STAGE_BYTES);
        attr_done = true;
    }

    // 0. precision splits
    prep_kernel<<<16384, 256>>>(x, wq, wk, wv, wo);

    // 1. QKV projection (fused N=3072), Q pre-scaled by 1/8
    qkv_gemm<<<dim3(3 * D_ / 64, BS_ / 128), 256, 2 * STAGE_BYTES>>>(bq, bk, bv);

    // 2. rowsum partials only (no P materialization)
    scores_lite<<<dim3(S_ / 64, S_ / 128, NBH_), 256, STAGE_BYTES>>>();

    // 3. inverse row sums
    inv_kernel<<<NBH_ * S_ / 256, 256>>>();

    // 4. fused: recompute S, write normalized attn, ctx = (P·V)·inv (split-K=2)
    pv_fused<<<dim3(2, S_ / 128, NBH_), 256, PV_SMEM>>>(attn);

    // 5. reduce ctx partials -> hi/lo
    ctx_reduce<<<BS_ * D_ / 512, 256>>>();

    // 6. out projection
    oproj_gemm<<<dim3(D_ / 64, BS_ / 128), 256, 2 * STAGE_BYTES>>>(bo, out);
}

// round 7
// speedup vs baseline: 1.1822x; 1.1822x over previous
#include <cuda_runtime.h>
#include <cuda_fp16.h>

#define B_   2
#define S_   2048
#define D_   1024
#define H_   16
#define DK_  64
#define BS_  (B_*S_)            // 4096
#define NBH_ (B_*H_)            // 32

// ---------------- device scratch (no allocations allowed) -------------------
__device__ __half g_xh[BS_ * D_],  g_xl[BS_ * D_];        // x fp16 hi/lo (A)
__device__ __half g_w3[3 * D_ * D_];                      // wq|wk|wv single (B)
__device__ __half g_wo[D_ * D_];                          // wo single (B)
__device__ __half g_qh[NBH_ * S_ * DK_], g_ql[NBH_ * S_ * DK_]; // Q hi/lo (A)
__device__ __half g_k1[NBH_ * S_ * DK_];                  // K single (B)
__device__ __half g_vt[NBH_ * DK_ * S_];                  // V^T single (B) [bh][d][s]
__device__ __half g_ch[BS_ * D_], g_cl[BS_ * D_];         // ctx hi/lo (A)
__device__ __half g_ph[(size_t)NBH_ * S_ * S_];           // exp(scores) hi (A)
__device__ __half g_pl[(size_t)NBH_ * S_ * S_];           // exp(scores) lo
__device__ float g_rsum_part[64][NBH_ * S_];              // deterministic partials
__device__ float g_inv[NBH_ * S_];                        // 1/rowsum
__device__ float g_ctxp[4 * BS_ * D_];                    // split-K ctx partials
__device__ float g_attn_fb[(size_t)NBH_ * S_ * S_];       // fallback

// ---------------- smem layout (per stage) -------------------------------
// A tile 128x64 fp16 hi (16KB) + lo (16KB) ; B tile 64x64 fp16 single (8KB)
#define OFF_AH 0
#define OFF_AL 16384
#define OFF_B  32768
#define STAGE_BYTES 40960

// ---------------- helpers ----------------------------------------------------
__device__ __forceinline__ unsigned smem_u32(const void* p) {
    return (unsigned)__cvta_generic_to_shared(p);
}
__device__ __forceinline__ void ldsm4(unsigned r[4], unsigned addr) {
    asm volatile("ldmatrix.sync.aligned.m8n8.x4.shared.b16 {%0,%1,%2,%3}, [%4];\n"
                 : "=r"(r[0]), "=r"(r[1]), "=r"(r[2]), "=r"(r[3]) : "r"(addr));
}
__device__ __forceinline__ void mma16816h(float (&d)[4], const unsigned a[4],
                                          unsigned b0, unsigned b1) {
    asm volatile(
        "mma.sync.aligned.m16n8k16.row.col.f32.f16.f16.f32 "
        "{%0,%1,%2,%3}, {%4,%5,%6,%7}, {%8,%9}, {%0,%1,%2,%3};\n"
        : "+f"(d[0]), "+f"(d[1]), "+f"(d[2]), "+f"(d[3])
        : "r"(a[0]), "r"(a[1]), "r"(a[2]), "r"(a[3]), "r"(b0), "r"(b1));
}
// split two floats into packed fp16 hi/lo (hi+lo represents fp32 to ~2^-22)
__device__ __forceinline__ void split2h(float x, float y, unsigned &h, unsigned &l) {
    __half2 hv = __floats2half2_rn(x, y);
    float rx = x - __low2float(hv);
    float ry = y - __high2float(hv);
    __half2 lv = __floats2half2_rn(rx, ry);
    h = *reinterpret_cast<unsigned*>(&hv);
    l = *reinterpret_cast<unsigned*>(&lv);
}
__device__ __forceinline__ unsigned pack_h2(float x, float y) {
    __half2 hv = __floats2half2_rn(x, y);
    return *reinterpret_cast<unsigned*>(&hv);
}
__device__ __forceinline__ unsigned swz(int row, int kb) {
    return (unsigned)(row * 128 + (kb ^ ((row & 7) << 4)));
}
__device__ __forceinline__ void cp16(unsigned dst, const void* src) {
    asm volatile("cp.async.cg.shared.global [%0], [%1], 16;\n" :: "r"(dst), "l"(src));
}
#define CP_COMMIT asm volatile("cp.async.commit_group;\n" ::: "memory")
#define CP_WAIT1  asm volatile("cp.async.wait_group 1;\n" ::: "memory")
#define CP_WAIT0  asm volatile("cp.async.wait_group 0;\n" ::: "memory")

// ---------------- cp.async tile staging ---------------------------------------
__device__ __forceinline__ void cpA_tile(unsigned AH, unsigned AL,
    const __half* __restrict__ Ah, const __half* __restrict__ Al,
    int ld, int m0, int k0, int tid)
{
#pragma unroll
    for (int j = 0; j < 4; j++) {
        int id = tid + j * 256, row = id >> 3, c = id & 7;
        size_t g = (size_t)(m0 + row) * ld + k0 + c * 8;
        unsigned o = swz(row, c * 16);
        cp16(AH + o, Ah + g);
        cp16(AL + o, Al + g);
    }
}
__device__ __forceinline__ void cpB1_tile(unsigned Bb,
    const __half* __restrict__ Bp, int ld, int n0, int k0, int tid)
{
#pragma unroll
    for (int j = 0; j < 2; j++) {
        int id = tid + j * 256, row = id >> 3, c = id & 7;
        size_t g = (size_t)(n0 + row) * ld + k0 + c * 8;
        cp16(Bb + swz(row, c * 16), Bp + g);
    }
}

// ---------------- core compute over one BK=64 stage ---------------------------
// A hi at aBase, A lo at aBase+16384 (128 rows); B single at bBase (64 rows)
__device__ __forceinline__ void compute_stage(unsigned aBase, unsigned bBase,
                                              int wm, int wn, int lane,
                                              float acc[2][4][4])
{
    const int arow0 = wm * 32 + (lane & 15);
    const int akh   = ((lane >> 4) & 1) * 16;
    const int brow0 = wn * 32 + ((lane >> 4) & 1) * 8 + (lane & 7);
    const int bkh   = ((lane >> 3) & 1) * 16;
#pragma unroll
    for (int ks = 0; ks < 4; ks++) {
        unsigned ah[2][4], al[2][4], bm[2][4];
#pragma unroll
        for (int mt = 0; mt < 2; mt++) {
            unsigned off = swz(arow0 + mt * 16, ks * 32 + akh);
            ldsm4(ah[mt], aBase + off);
            ldsm4(al[mt], aBase + 16384 + off);
        }
#pragma unroll
        for (int p = 0; p < 2; p++) {
            unsigned off = swz(brow0 + p * 16, ks * 32 + bkh);
            ldsm4(bm[p], bBase + off);
        }
#pragma unroll
        for (int mt = 0; mt < 2; mt++)
#pragma unroll
            for (int nt = 0; nt < 4; nt++) {
                unsigned b0 = bm[nt >> 1][(nt & 1) * 2], b1 = bm[nt >> 1][(nt & 1) * 2 + 1];
                mma16816h(acc[mt][nt], ah[mt], b0, b1);
                mma16816h(acc[mt][nt], al[mt], b0, b1);
            }
    }
}

// ---------------- prep: fp32 -> fp16 splits / casts ----------------------------
__global__ void prep_kernel(const float* __restrict__ x,
                            const float* __restrict__ wq,
                            const float* __restrict__ wk,
                            const float* __restrict__ wv,
                            const float* __restrict__ wo)
{
    const int bid = blockIdx.x, tid = threadIdx.x;
    if (bid < 8192) {   // x -> hi/lo
        int i = (bid * 256 + tid) * 2;
        unsigned h, l;
        split2h(x[i], x[i + 1], h, l);
        *reinterpret_cast<unsigned*>(g_xh + i) = h;
        *reinterpret_cast<unsigned*>(g_xl + i) = l;
        return;
    }
    const float* src;
    __half* dst;
    int base;
    if (bid < 10240)      { src = wq; dst = g_w3;             base = 8192;  }
    else if (bid < 12288) { src = wk; dst = g_w3 + D_*D_;     base = 10240; }
    else if (bid < 14336) { src = wv; dst = g_w3 + 2*D_*D_;   base = 12288; }
    else                  { src = wo; dst = g_wo;             base = 14336; }
    int i = ((bid - base) * 256 + tid) * 2;
    *reinterpret_cast<unsigned*>(dst + i) = pack_h2(src[i], src[i + 1]);
}

// =============================================================================
// Kernel 1: fused QKV projection; Q pre-scaled by 1/8, stored hi/lo;
// K stored single fp16; V stored transposed single fp16
// =============================================================================
__global__ __launch_bounds__(256, 2) void qkv_gemm(const float* __restrict__ bq,
                                                   const float* __restrict__ bk,
                                                   const float* __restrict__ bv)
{
    extern __shared__ char sm[];
    const unsigned sb = smem_u32(sm);
    const int m0 = blockIdx.y * 128, n0 = blockIdx.x * 64;
    const int tid = threadIdx.x, lane = tid & 31, wid = tid >> 5;
    const int wm = wid >> 1, wn = wid & 1;
    float acc[2][4][4] = {};

    cpA_tile(sb + OFF_AH, sb + OFF_AL, g_xh, g_xl, D_, m0, 0, tid);
    cpB1_tile(sb + OFF_B, g_w3, D_, n0, 0, tid);
    CP_COMMIT;
    for (int it = 0; it < 16; it++) {
        const unsigned cb = sb + (it & 1) * STAGE_BYTES;
        if (it + 1 < 16) {
            const unsigned nb = sb + ((it + 1) & 1) * STAGE_BYTES;
            cpA_tile(nb + OFF_AH, nb + OFF_AL, g_xh, g_xl, D_, m0, (it + 1) * 64, tid);
            cpB1_tile(nb + OFF_B, g_w3, D_, n0, (it + 1) * 64, tid);
            CP_COMMIT;
            CP_WAIT1;
        } else { CP_WAIT0; }
        __syncthreads();
        compute_stage(cb + OFF_AH, cb + OFF_B, wm, wn, lane, acc);
        __syncthreads();
    }

    const int reg = n0 >> 10;                 // 0=Q,1=K,2=V
    const int h   = (n0 & 1023) >> 6;
    const float* bp = (reg == 0) ? bq : (reg == 1) ? bk : bv;
    const float scale = (reg == 0) ? 0.125f : 1.0f;
    const int tm0 = m0 + wm * 32, tn0 = n0 + wn * 32;

#pragma unroll
    for (int mt = 0; mt < 2; mt++)
#pragma unroll
        for (int nt = 0; nt < 4; nt++) {
            const int c  = tn0 + nt * 8 + 2 * (lane & 3);
            const int d  = c & 63;
            const float bias0 = bp[c & 1023], bias1 = bp[(c & 1023) + 1];
#pragma unroll
            for (int half = 0; half < 2; half++) {
                const int m = tm0 + mt * 16 + (lane >> 2) + half * 8;
                const float v0 = (acc[mt][nt][half * 2]     + bias0) * scale;
                const float v1 = (acc[mt][nt][half * 2 + 1] + bias1) * scale;
                const int b = m >> 11, s = m & 2047;
                const size_t bh = (size_t)(b * H_ + h);
                if (reg == 0) {            // Q hi/lo
                    unsigned hh, ll;
                    split2h(v0, v1, hh, ll);
                    size_t idx = (bh * S_ + s) * DK_ + d;
                    *reinterpret_cast<unsigned*>(g_qh + idx) = hh;
                    *reinterpret_cast<unsigned*>(g_ql + idx) = ll;
                } else if (reg == 1) {     // K single
                    size_t idx = (bh * S_ + s) * DK_ + d;
                    *reinterpret_cast<unsigned*>(g_k1 + idx) = pack_h2(v0, v1);
                } else {                   // V^T single
                    size_t i0 = (bh * DK_ + d) * S_ + s;
                    g_vt[i0]      = __float2half(v0);
                    g_vt[i0 + S_] = __float2half(v1);
                }
            }
        }
}

// =============================================================================
// Kernel 2: P = exp(QK^T/8) as fp16 hi/lo + deterministic partial row sums
// =============================================================================
__global__ __launch_bounds__(256) void scores_gemm()
{
    extern __shared__ char sm[];
    const unsigned sb = smem_u32(sm);
    const int bh = blockIdx.z;
    const int m0 = blockIdx.y * 128, n0 = blockIdx.x * 64;
    const int tid = threadIdx.x, lane = tid & 31, wid = tid >> 5;
    const int wm = wid >> 1, wn = wid & 1;

    const __half* Ah = g_qh + (size_t)bh * S_ * DK_;
    const __half* Al = g_ql + (size_t)bh * S_ * DK_;
    const __half* Bp = g_k1 + (size_t)bh * S_ * DK_;

    float acc[2][4][4] = {};
    cpA_tile(sb + OFF_AH, sb + OFF_AL, Ah, Al, DK_, m0, 0, tid);
    cpB1_tile(sb + OFF_B, Bp, DK_, n0, 0, tid);
    CP_COMMIT;
    CP_WAIT0;
    __syncthreads();
    compute_stage(sb + OFF_AH, sb + OFF_B, wm, wn, lane, acc);

    __half* Ph = g_ph + (size_t)bh * S_ * S_;
    __half* Pl = g_pl + (size_t)bh * S_ * S_;
    const int tm0 = m0 + wm * 32, tn0 = n0 + wn * 32;
    float rpart[2][2] = {};
#pragma unroll
    for (int mt = 0; mt < 2; mt++)
#pragma unroll
        for (int nt = 0; nt < 4; nt++) {
            const int c = tn0 + nt * 8 + 2 * (lane & 3);
#pragma unroll
            for (int half = 0; half < 2; half++) {
                const int m = tm0 + mt * 16 + (lane >> 2) + half * 8;
                const float e0 = __expf(acc[mt][nt][half * 2]);
                const float e1 = __expf(acc[mt][nt][half * 2 + 1]);
                unsigned hh, ll;
                split2h(e0, e1, hh, ll);
                size_t idx = (size_t)m * S_ + c;
                *reinterpret_cast<unsigned*>(Ph + idx) = hh;
                *reinterpret_cast<unsigned*>(Pl + idx) = ll;
                rpart[mt][half] += e0 + e1;
            }
        }

    const int slot = blockIdx.x * 2 + wn;
#pragma unroll
    for (int mt = 0; mt < 2; mt++)
#pragma unroll
        for (int half = 0; half < 2; half++) {
            float v = rpart[mt][half];
            v += __shfl_xor_sync(0xffffffffu, v, 1);
            v += __shfl_xor_sync(0xffffffffu, v, 2);
            if ((lane & 3) == 0) {
                const int m = tm0 + mt * 16 + (lane >> 2) + half * 8;
                g_rsum_part[slot][(size_t)bh * S_ + m] = v;
            }
        }
}

// ---------------- inv_kernel: 1/rowsum from 64 partials ------------------------
__global__ void inv_kernel()
{
    const int r = blockIdx.x * 256 + threadIdx.x;   // 65536 rows
    float s = 0.f;
#pragma unroll
    for (int p = 0; p < 64; p++) s += g_rsum_part[p][r];
    g_inv[r] = 1.0f / s;
}

// =============================================================================
// Kernel 3: pv split-K: partial ctx = (P·V)·inv ; also writes normalized attn fp32
// grid (kz=4, mtile=16, bh=32)
// =============================================================================
__global__ __launch_bounds__(256, 2) void pv_gemm(float* __restrict__ attn_arg)
{
    extern __shared__ char sm[];
    __shared__ float s_inv[128];
    const unsigned sb = smem_u32(sm);
    float* attn = attn_arg ? attn_arg : g_attn_fb;
    const int kz = blockIdx.x, bh = blockIdx.z;
    const int m0 = blockIdx.y * 128;
    const int tid = threadIdx.x, lane = tid & 31, wid = tid >> 5;
    const int wm = wid >> 1, wn = wid & 1;

    if (tid < 128) s_inv[tid] = g_inv[(size_t)bh * S_ + m0 + tid];

    const __half* Ph = g_ph + (size_t)bh * S_ * S_;
    const __half* Pl = g_pl + (size_t)bh * S_ * S_;
    const __half* Vp = g_vt + (size_t)bh * DK_ * S_;
    float* Aout = attn + (size_t)bh * S_ * S_;

    float acc[2][4][4] = {};
    const int kbase = kz * 512;

    cpA_tile(sb + OFF_AH, sb + OFF_AL, Ph, Pl, S_, m0, kbase, tid);
    cpB1_tile(sb + OFF_B, Vp, S_, 0, kbase, tid);
    CP_COMMIT;
    for (int it = 0; it < 8; it++) {
        const int cur = it & 1;
        const unsigned cb = sb + cur * STAGE_BYTES;
        const int k0 = kbase + it * 64;
        if (it + 1 < 8) {
            const unsigned nb = sb + (1 - cur) * STAGE_BYTES;
            cpA_tile(nb + OFF_AH, nb + OFF_AL, Ph, Pl, S_, m0, k0 + 64, tid);
            cpB1_tile(nb + OFF_B, Vp, S_, 0, k0 + 64, tid);
            CP_COMMIT;
            CP_WAIT1;
        } else { CP_WAIT0; }
        __syncthreads();

        // write normalized attn fp32 from this stage's A tile (each elem once)
        const char* cbc = sm + cur * STAGE_BYTES;
#pragma unroll
        for (int j = 0; j < 4; j++) {
            int id = tid + j * 256, row = id >> 3, c = id & 7;
            unsigned off = swz(row, c * 16);
            uint4 hv = *reinterpret_cast<const uint4*>(cbc + OFF_AH + off);
            uint4 lv = *reinterpret_cast<const uint4*>(cbc + OFF_AL + off);
            const float inv = s_inv[row];
            float4 o0, o1;
            float2 fh, fl;
            fh = __half22float2(*reinterpret_cast<__half2*>(&hv.x));
            fl = __half22float2(*reinterpret_cast<__half2*>(&lv.x));
            o0.x = (fh.x + fl.x) * inv;  o0.y = (fh.y + fl.y) * inv;
            fh = __half22float2(*reinterpret_cast<__half2*>(&hv.y));
            fl = __half22float2(*reinterpret_cast<__half2*>(&lv.y));
            o0.z = (fh.x + fl.x) * inv;  o0.w = (fh.y + fl.y) * inv;
            fh = __half22float2(*reinterpret_cast<__half2*>(&hv.z));
            fl = __half22float2(*reinterpret_cast<__half2*>(&lv.z));
            o1.x = (fh.x + fl.x) * inv;  o1.y = (fh.y + fl.y) * inv;
            fh = __half22float2(*reinterpret_cast<__half2*>(&hv.w));
            fl = __half22float2(*reinterpret_cast<__half2*>(&lv.w));
            o1.z = (fh.x + fl.x) * inv;  o1.w = (fh.y + fl.y) * inv;
            float* dst = Aout + (size_t)(m0 + row) * S_ + k0 + c * 8;
            *reinterpret_cast<float4*>(dst)     = o0;
            *reinterpret_cast<float4*>(dst + 4) = o1;
        }

        compute_stage(cb + OFF_AH, cb + OFF_B, wm, wn, lane, acc);
        __syncthreads();
    }

    // epilogue: fp32 partial ctx scaled by inv (linear => valid per partial)
    const int b = bh >> 4, h = bh & 15;
    float* dst = g_ctxp + (size_t)kz * BS_ * D_;
#pragma unroll
    for (int mt = 0; mt < 2; mt++)
#pragma unroll
        for (int nt = 0; nt < 4; nt++) {
            const int c = wn * 32 + nt * 8 + 2 * (lane & 3);
#pragma unroll
            for (int half = 0; half < 2; half++) {
                const int rowl = wm * 32 + mt * 16 + (lane >> 2) + half * 8;
                const float inv = s_inv[rowl];
                const int s = m0 + rowl;
                float2 v = { acc[mt][nt][half * 2] * inv,
                             acc[mt][nt][half * 2 + 1] * inv };
                *reinterpret_cast<float2*>(&dst[(size_t)(b * S_ + s) * D_ + h * DK_ + c]) = v;
            }
        }
}

// ---------------- ctx reduce: sum 4 partials -> hi/lo fp16 ---------------------
__global__ void ctx_reduce()
{
    const size_t i = ((size_t)blockIdx.x * 256 + threadIdx.x) * 2;
    float2 s = {0.f, 0.f};
#pragma unroll
    for (int p = 0; p < 4; p++) {
        float2 v = *reinterpret_cast<const float2*>(&g_ctxp[(size_t)p * BS_ * D_ + i]);
        s.x += v.x; s.y += v.y;
    }
    unsigned hh, ll;
    split2h(s.x, s.y, hh, ll);
    *reinterpret_cast<unsigned*>(g_ch + i) = hh;
    *reinterpret_cast<unsigned*>(g_cl + i) = ll;
}

// =============================================================================
// Kernel 4: out = ctx @ Wo^T + bo
// =============================================================================
__global__ __launch_bounds__(256, 2) void oproj_gemm(const float* __restrict__ bo,
                                                     float* __restrict__ out)
{
    extern __shared__ char sm[];
    const unsigned sb = smem_u32(sm);
    const int m0 = blockIdx.y * 128, n0 = blockIdx.x * 64;
    const int tid = threadIdx.x, lane = tid & 31, wid = tid >> 5;
    const int wm = wid >> 1, wn = wid & 1;
    float acc[2][4][4] = {};

    cpA_tile(sb + OFF_AH, sb + OFF_AL, g_ch, g_cl, D_, m0, 0, tid);
    cpB1_tile(sb + OFF_B, g_wo, D_, n0, 0, tid);
    CP_COMMIT;
    for (int it = 0; it < 16; it++) {
        const unsigned cb = sb + (it & 1) * STAGE_BYTES;
        if (it + 1 < 16) {
            const unsigned nb = sb + ((it + 1) & 1) * STAGE_BYTES;
            cpA_tile(nb + OFF_AH, nb + OFF_AL, g_ch, g_cl, D_, m0, (it + 1) * 64, tid);
            cpB1_tile(nb + OFF_B, g_wo, D_, n0, (it + 1) * 64, tid);
            CP_COMMIT;
            CP_WAIT1;
        } else { CP_WAIT0; }
        __syncthreads();
        compute_stage(cb + OFF_AH, cb + OFF_B, wm, wn, lane, acc);
        __syncthreads();
    }

    const int tm0 = m0 + wm * 32, tn0 = n0 + wn * 32;
#pragma unroll
    for (int mt = 0; mt < 2; mt++)
#pragma unroll
        for (int nt = 0; nt < 4; nt++) {
            const int c = tn0 + nt * 8 + 2 * (lane & 3);
            const float b0 = bo[c], b1 = bo[c + 1];
#pragma unroll
            for (int half = 0; half < 2; half++) {
                const int m = tm0 + mt * 16 + (lane >> 2) + half * 8;
                float2 v = { acc[mt][nt][half * 2] + b0,
                             acc[mt][nt][half * 2 + 1] + b1 };
                *reinterpret_cast<float2*>(out + (size_t)m * D_ + c) = v;
            }
        }
}

// =============================================================================
extern "C" void kernel_launch(void* const* d_in, const int* in_sizes, int n_in,
                              void* d_out, int out_size)
{
    const float* x  = (const float*)d_in[0];
    const float* wq = (const float*)d_in[1];
    const float* bq = (const float*)d_in[2];
    const float* wk = (const float*)d_in[3];
    const float* bk = (const float*)d_in[4];
    const float* wv = (const float*)d_in[5];
    const float* bv = (const float*)d_in[6];
    const float* wo = (const float*)d_in[7];
    const float* bo = (const float*)d_in[8];

    float* out = (float*)d_out;
    const long long OUT_E  = (long long)BS_ * D_;
    const long long ATTN_E = (long long)NBH_ * S_ * S_;
    float* attn = ((long long)out_size >= OUT_E + ATTN_E) ? (out + OUT_E) : nullptr;

    static bool attr_done = false;
    if (!attr_done) {
        cudaFuncSetAttribute(qkv_gemm,    cudaFuncAttributeMaxDynamicSharedMemorySize, 2 * STAGE_BYTES);
        cudaFuncSetAttribute(pv_gemm,     cudaFuncAttributeMaxDynamicSharedMemorySize, 2 * STAGE_BYTES);
        cudaFuncSetAttribute(oproj_gemm,  cudaFuncAttributeMaxDynamicSharedMemorySize, 2 * STAGE_BYTES);
        cudaFuncSetAttribute(scores_gemm, cudaFuncAttributeMaxDynamicSharedMemorySize, STAGE_BYTES);
        attr_done = true;
    }

    // 0. precision splits / casts
    prep_kernel<<<16384, 256>>>(x, wq, wk, wv, wo);

    // 1. QKV projection (fused N=3072), Q pre-scaled by 1/8
    qkv_gemm<<<dim3(3 * D_ / 64, BS_ / 128), 256, 2 * STAGE_BYTES>>>(bq, bk, bv);

    // 2. P = exp(QK^T/8) fp16 hi/lo + deterministic partial row sums
    scores_gemm<<<dim3(S_ / 64, S_ / 128, NBH_), 256, STAGE_BYTES>>>();

    // 3. inverse row sums
    inv_kernel<<<NBH_ * S_ / 256, 256>>>();

    // 4. pv split-K=4: partial ctx + normalized attn fp32 output
    pv_gemm<<<dim3(4, S_ / 128, NBH_), 256, 2 * STAGE_BYTES>>>(attn);

    // 5. reduce ctx partials -> hi/lo
    ctx_reduce<<<BS_ * D_ / 512, 256>>>();

    // 6. out projection
    oproj_gemm<<<dim3(D_ / 64, BS_ / 128), 256, 2 * STAGE_BYTES>>>(bo, out);
}

// round 8
// speedup vs baseline: 1.4197x; 1.2008x over previous
#include <cuda_runtime.h>
#include <cuda_fp16.h>

#define B_   2
#define S_   2048
#define D_   1024
#define H_   16
#define DK_  64
#define BS_  (B_*S_)            // 4096
#define NBH_ (B_*H_)            // 32

// ---------------- device scratch (no allocations allowed) -------------------
__device__ __half g_xh[BS_ * D_],  g_xl[BS_ * D_];        // x fp16 hi/lo (A)
__device__ __half g_w3[3 * D_ * D_];                      // wq|wk|wv single (B)
__device__ __half g_wo[D_ * D_];                          // wo single (B)
__device__ __half g_qh[NBH_ * S_ * DK_], g_ql[NBH_ * S_ * DK_]; // Q hi/lo (A)
__device__ __half g_k1[NBH_ * S_ * DK_];                  // K single (B)
__device__ __half g_vt[NBH_ * DK_ * S_];                  // V^T single (B) [bh][d][s]
__device__ __half g_c1[BS_ * D_];                         // ctx single (A)
__device__ __half g_p1[(size_t)NBH_ * S_ * S_];           // exp(scores) single (A)
__device__ float g_rsum_part[64][NBH_ * S_];              // deterministic partials
__device__ float g_inv[NBH_ * S_];                        // 1/rowsum
__device__ float g_ctxp[4 * BS_ * D_];                    // split-K ctx partials
__device__ float g_attn_fb[(size_t)NBH_ * S_ * S_];       // fallback

// ---------------- smem layouts -------------------------------------------------
// hi/lo GEMMs (qkv, scores): A hi 16K + A lo 16K + B 8K
#define OFF_AH 0
#define OFF_AL 16384
#define OFF_B  32768
#define STAGE_BYTES 40960
// single-A GEMMs (pv, oproj): A 16K + B 8K
#define OFF1_A 0
#define OFF1_B 16384
#define STAGE1_BYTES 24576

// ---------------- helpers ----------------------------------------------------
__device__ __forceinline__ unsigned smem_u32(const void* p) {
    return (unsigned)__cvta_generic_to_shared(p);
}
__device__ __forceinline__ void ldsm4(unsigned r[4], unsigned addr) {
    asm volatile("ldmatrix.sync.aligned.m8n8.x4.shared.b16 {%0,%1,%2,%3}, [%4];\n"
                 : "=r"(r[0]), "=r"(r[1]), "=r"(r[2]), "=r"(r[3]) : "r"(addr));
}
__device__ __forceinline__ void mma16816h(float (&d)[4], const unsigned a[4],
                                          unsigned b0, unsigned b1) {
    asm volatile(
        "mma.sync.aligned.m16n8k16.row.col.f32.f16.f16.f32 "
        "{%0,%1,%2,%3}, {%4,%5,%6,%7}, {%8,%9}, {%0,%1,%2,%3};\n"
        : "+f"(d[0]), "+f"(d[1]), "+f"(d[2]), "+f"(d[3])
        : "r"(a[0]), "r"(a[1]), "r"(a[2]), "r"(a[3]), "r"(b0), "r"(b1));
}
__device__ __forceinline__ void split2h(float x, float y, unsigned &h, unsigned &l) {
    __half2 hv = __floats2half2_rn(x, y);
    float rx = x - __low2float(hv);
    float ry = y - __high2float(hv);
    __half2 lv = __floats2half2_rn(rx, ry);
    h = *reinterpret_cast<unsigned*>(&hv);
    l = *reinterpret_cast<unsigned*>(&lv);
}
__device__ __forceinline__ unsigned pack_h2(float x, float y) {
    __half2 hv = __floats2half2_rn(x, y);
    return *reinterpret_cast<unsigned*>(&hv);
}
__device__ __forceinline__ unsigned swz(int row, int kb) {
    return (unsigned)(row * 128 + (kb ^ ((row & 7) << 4)));
}
__device__ __forceinline__ void cp16(unsigned dst, const void* src) {
    asm volatile("cp.async.cg.shared.global [%0], [%1], 16;\n" :: "r"(dst), "l"(src));
}
#define CP_COMMIT asm volatile("cp.async.commit_group;\n" ::: "memory")
#define CP_WAIT1  asm volatile("cp.async.wait_group 1;\n" ::: "memory")
#define CP_WAIT0  asm volatile("cp.async.wait_group 0;\n" ::: "memory")

// ---------------- cp.async tile staging ---------------------------------------
__device__ __forceinline__ void cpA_tile(unsigned AH, unsigned AL,
    const __half* __restrict__ Ah, const __half* __restrict__ Al,
    int ld, int m0, int k0, int tid)
{
#pragma unroll
    for (int j = 0; j < 4; j++) {
        int id = tid + j * 256, row = id >> 3, c = id & 7;
        size_t g = (size_t)(m0 + row) * ld + k0 + c * 8;
        unsigned o = swz(row, c * 16);
        cp16(AH + o, Ah + g);
        cp16(AL + o, Al + g);
    }
}
__device__ __forceinline__ void cpA1_tile(unsigned Ab,
    const __half* __restrict__ Ap, int ld, int m0, int k0, int tid)
{
#pragma unroll
    for (int j = 0; j < 4; j++) {
        int id = tid + j * 256, row = id >> 3, c = id & 7;
        size_t g = (size_t)(m0 + row) * ld + k0 + c * 8;
        cp16(Ab + swz(row, c * 16), Ap + g);
    }
}
__device__ __forceinline__ void cpB1_tile(unsigned Bb,
    const __half* __restrict__ Bp, int ld, int n0, int k0, int tid)
{
#pragma unroll
    for (int j = 0; j < 2; j++) {
        int id = tid + j * 256, row = id >> 3, c = id & 7;
        size_t g = (size_t)(n0 + row) * ld + k0 + c * 8;
        cp16(Bb + swz(row, c * 16), Bp + g);
    }
}

// ---------------- compute: A hi/lo (2 MMA) ------------------------------------
__device__ __forceinline__ void compute_stage(unsigned aBase, unsigned bBase,
                                              int wm, int wn, int lane,
                                              float acc[2][4][4])
{
    const int arow0 = wm * 32 + (lane & 15);
    const int akh   = ((lane >> 4) & 1) * 16;
    const int brow0 = wn * 32 + ((lane >> 4) & 1) * 8 + (lane & 7);
    const int bkh   = ((lane >> 3) & 1) * 16;
#pragma unroll
    for (int ks = 0; ks < 4; ks++) {
        unsigned ah[2][4], al[2][4], bm[2][4];
#pragma unroll
        for (int mt = 0; mt < 2; mt++) {
            unsigned off = swz(arow0 + mt * 16, ks * 32 + akh);
            ldsm4(ah[mt], aBase + off);
            ldsm4(al[mt], aBase + 16384 + off);
        }
#pragma unroll
        for (int p = 0; p < 2; p++) {
            unsigned off = swz(brow0 + p * 16, ks * 32 + bkh);
            ldsm4(bm[p], bBase + off);
        }
#pragma unroll
        for (int mt = 0; mt < 2; mt++)
#pragma unroll
            for (int nt = 0; nt < 4; nt++) {
                unsigned b0 = bm[nt >> 1][(nt & 1) * 2], b1 = bm[nt >> 1][(nt & 1) * 2 + 1];
                mma16816h(acc[mt][nt], ah[mt], b0, b1);
                mma16816h(acc[mt][nt], al[mt], b0, b1);
            }
    }
}
// ---------------- compute: A single (1 MMA) ------------------------------------
__device__ __forceinline__ void compute_stage1(unsigned aBase, unsigned bBase,
                                               int wm, int wn, int lane,
                                               float acc[2][4][4])
{
    const int arow0 = wm * 32 + (lane & 15);
    const int akh   = ((lane >> 4) & 1) * 16;
    const int brow0 = wn * 32 + ((lane >> 4) & 1) * 8 + (lane & 7);
    const int bkh   = ((lane >> 3) & 1) * 16;
#pragma unroll
    for (int ks = 0; ks < 4; ks++) {
        unsigned am[2][4], bm[2][4];
#pragma unroll
        for (int mt = 0; mt < 2; mt++)
            ldsm4(am[mt], aBase + swz(arow0 + mt * 16, ks * 32 + akh));
#pragma unroll
        for (int p = 0; p < 2; p++)
            ldsm4(bm[p], bBase + swz(brow0 + p * 16, ks * 32 + bkh));
#pragma unroll
        for (int mt = 0; mt < 2; mt++)
#pragma unroll
            for (int nt = 0; nt < 4; nt++)
                mma16816h(acc[mt][nt], am[mt],
                          bm[nt >> 1][(nt & 1) * 2], bm[nt >> 1][(nt & 1) * 2 + 1]);
    }
}

// ---------------- prep: fp32 -> fp16 splits / casts ----------------------------
__global__ void prep_kernel(const float* __restrict__ x,
                            const float* __restrict__ wq,
                            const float* __restrict__ wk,
                            const float* __restrict__ wv,
                            const float* __restrict__ wo)
{
    const int bid = blockIdx.x, tid = threadIdx.x;
    if (bid < 8192) {   // x -> hi/lo
        int i = (bid * 256 + tid) * 2;
        unsigned h, l;
        split2h(x[i], x[i + 1], h, l);
        *reinterpret_cast<unsigned*>(g_xh + i) = h;
        *reinterpret_cast<unsigned*>(g_xl + i) = l;
        return;
    }
    const float* src;
    __half* dst;
    int base;
    if (bid < 10240)      { src = wq; dst = g_w3;             base = 8192;  }
    else if (bid < 12288) { src = wk; dst = g_w3 + D_*D_;     base = 10240; }
    else if (bid < 14336) { src = wv; dst = g_w3 + 2*D_*D_;   base = 12288; }
    else                  { src = wo; dst = g_wo;             base = 14336; }
    int i = ((bid - base) * 256 + tid) * 2;
    *reinterpret_cast<unsigned*>(dst + i) = pack_h2(src[i], src[i + 1]);
}

// =============================================================================
// Kernel 1: fused QKV projection; Q pre-scaled by 1/8 hi/lo; K single; V^T single
// =============================================================================
__global__ __launch_bounds__(256, 2) void qkv_gemm(const float* __restrict__ bq,
                                                   const float* __restrict__ bk,
                                                   const float* __restrict__ bv)
{
    extern __shared__ char sm[];
    const unsigned sb = smem_u32(sm);
    const int m0 = blockIdx.y * 128, n0 = blockIdx.x * 64;
    const int tid = threadIdx.x, lane = tid & 31, wid = tid >> 5;
    const int wm = wid >> 1, wn = wid & 1;
    float acc[2][4][4] = {};

    cpA_tile(sb + OFF_AH, sb + OFF_AL, g_xh, g_xl, D_, m0, 0, tid);
    cpB1_tile(sb + OFF_B, g_w3, D_, n0, 0, tid);
    CP_COMMIT;
    for (int it = 0; it < 16; it++) {
        const unsigned cb = sb + (it & 1) * STAGE_BYTES;
        if (it + 1 < 16) {
            const unsigned nb = sb + ((it + 1) & 1) * STAGE_BYTES;
            cpA_tile(nb + OFF_AH, nb + OFF_AL, g_xh, g_xl, D_, m0, (it + 1) * 64, tid);
            cpB1_tile(nb + OFF_B, g_w3, D_, n0, (it + 1) * 64, tid);
            CP_COMMIT;
            CP_WAIT1;
        } else { CP_WAIT0; }
        __syncthreads();
        compute_stage(cb + OFF_AH, cb + OFF_B, wm, wn, lane, acc);
        __syncthreads();
    }

    const int reg = n0 >> 10;                 // 0=Q,1=K,2=V
    const int h   = (n0 & 1023) >> 6;
    const float* bp = (reg == 0) ? bq : (reg == 1) ? bk : bv;
    const float scale = (reg == 0) ? 0.125f : 1.0f;
    const int tm0 = m0 + wm * 32, tn0 = n0 + wn * 32;

#pragma unroll
    for (int mt = 0; mt < 2; mt++)
#pragma unroll
        for (int nt = 0; nt < 4; nt++) {
            const int c  = tn0 + nt * 8 + 2 * (lane & 3);
            const int d  = c & 63;
            const float bias0 = bp[c & 1023], bias1 = bp[(c & 1023) + 1];
#pragma unroll
            for (int half = 0; half < 2; half++) {
                const int m = tm0 + mt * 16 + (lane >> 2) + half * 8;
                const float v0 = (acc[mt][nt][half * 2]     + bias0) * scale;
                const float v1 = (acc[mt][nt][half * 2 + 1] + bias1) * scale;
                const int b = m >> 11, s = m & 2047;
                const size_t bh = (size_t)(b * H_ + h);
                if (reg == 0) {
                    unsigned hh, ll;
                    split2h(v0, v1, hh, ll);
                    size_t idx = (bh * S_ + s) * DK_ + d;
                    *reinterpret_cast<unsigned*>(g_qh + idx) = hh;
                    *reinterpret_cast<unsigned*>(g_ql + idx) = ll;
                } else if (reg == 1) {
                    size_t idx = (bh * S_ + s) * DK_ + d;
                    *reinterpret_cast<unsigned*>(g_k1 + idx) = pack_h2(v0, v1);
                } else {
                    size_t i0 = (bh * DK_ + d) * S_ + s;
                    g_vt[i0]      = __float2half(v0);
                    g_vt[i0 + S_] = __float2half(v1);
                }
            }
        }
}

// =============================================================================
// Kernel 2: P = exp(QK^T/8) single fp16 + deterministic partial row sums
// =============================================================================
__global__ __launch_bounds__(256) void scores_gemm()
{
    extern __shared__ char sm[];
    const unsigned sb = smem_u32(sm);
    const int bh = blockIdx.z;
    const int m0 = blockIdx.y * 128, n0 = blockIdx.x * 64;
    const int tid = threadIdx.x, lane = tid & 31, wid = tid >> 5;
    const int wm = wid >> 1, wn = wid & 1;

    const __half* Ah = g_qh + (size_t)bh * S_ * DK_;
    const __half* Al = g_ql + (size_t)bh * S_ * DK_;
    const __half* Bp = g_k1 + (size_t)bh * S_ * DK_;

    float acc[2][4][4] = {};
    cpA_tile(sb + OFF_AH, sb + OFF_AL, Ah, Al, DK_, m0, 0, tid);
    cpB1_tile(sb + OFF_B, Bp, DK_, n0, 0, tid);
    CP_COMMIT;
    CP_WAIT0;
    __syncthreads();
    compute_stage(sb + OFF_AH, sb + OFF_B, wm, wn, lane, acc);

    __half* Pp = g_p1 + (size_t)bh * S_ * S_;
    const int tm0 = m0 + wm * 32, tn0 = n0 + wn * 32;
    float rpart[2][2] = {};
#pragma unroll
    for (int mt = 0; mt < 2; mt++)
#pragma unroll
        for (int nt = 0; nt < 4; nt++) {
            const int c = tn0 + nt * 8 + 2 * (lane & 3);
#pragma unroll
            for (int half = 0; half < 2; half++) {
                const int m = tm0 + mt * 16 + (lane >> 2) + half * 8;
                const float e0 = __expf(acc[mt][nt][half * 2]);
                const float e1 = __expf(acc[mt][nt][half * 2 + 1]);
                *reinterpret_cast<unsigned*>(Pp + (size_t)m * S_ + c) = pack_h2(e0, e1);
                rpart[mt][half] += e0 + e1;
            }
        }

    const int slot = blockIdx.x * 2 + wn;
#pragma unroll
    for (int mt = 0; mt < 2; mt++)
#pragma unroll
        for (int half = 0; half < 2; half++) {
            float v = rpart[mt][half];
            v += __shfl_xor_sync(0xffffffffu, v, 1);
            v += __shfl_xor_sync(0xffffffffu, v, 2);
            if ((lane & 3) == 0) {
                const int m = tm0 + mt * 16 + (lane >> 2) + half * 8;
                g_rsum_part[slot][(size_t)bh * S_ + m] = v;
            }
        }
}

// ---------------- inv_kernel: 1/rowsum from 64 partials ------------------------
__global__ void inv_kernel()
{
    const int r = blockIdx.x * 256 + threadIdx.x;   // 65536 rows
    float s = 0.f;
#pragma unroll
    for (int p = 0; p < 64; p++) s += g_rsum_part[p][r];
    g_inv[r] = 1.0f / s;
}

// =============================================================================
// Kernel 3: pv split-K=4: partial ctx = (P·V)·inv ; writes normalized attn fp32
// =============================================================================
__global__ __launch_bounds__(256, 2) void pv_gemm(float* __restrict__ attn_arg)
{
    extern __shared__ char sm[];
    __shared__ float s_inv[128];
    const unsigned sb = smem_u32(sm);
    float* attn = attn_arg ? attn_arg : g_attn_fb;
    const int kz = blockIdx.x, bh = blockIdx.z;
    const int m0 = blockIdx.y * 128;
    const int tid = threadIdx.x, lane = tid & 31, wid = tid >> 5;
    const int wm = wid >> 1, wn = wid & 1;

    if (tid < 128) s_inv[tid] = g_inv[(size_t)bh * S_ + m0 + tid];

    const __half* Pp = g_p1 + (size_t)bh * S_ * S_;
    const __half* Vp = g_vt + (size_t)bh * DK_ * S_;
    float* Aout = attn + (size_t)bh * S_ * S_;

    float acc[2][4][4] = {};
    const int kbase = kz * 512;

    cpA1_tile(sb + OFF1_A, Pp, S_, m0, kbase, tid);
    cpB1_tile(sb + OFF1_B, Vp, S_, 0, kbase, tid);
    CP_COMMIT;
    for (int it = 0; it < 8; it++) {
        const int cur = it & 1;
        const unsigned cb = sb + cur * STAGE1_BYTES;
        const int k0 = kbase + it * 64;
        if (it + 1 < 8) {
            const unsigned nb = sb + (1 - cur) * STAGE1_BYTES;
            cpA1_tile(nb + OFF1_A, Pp, S_, m0, k0 + 64, tid);
            cpB1_tile(nb + OFF1_B, Vp, S_, 0, k0 + 64, tid);
            CP_COMMIT;
            CP_WAIT1;
        } else { CP_WAIT0; }
        __syncthreads();

        // write normalized attn fp32 from this stage's A tile (each elem once)
        const char* cbc = sm + cur * STAGE1_BYTES;
#pragma unroll
        for (int j = 0; j < 4; j++) {
            int id = tid + j * 256, row = id >> 3, c = id & 7;
            uint4 pv4 = *reinterpret_cast<const uint4*>(cbc + OFF1_A + swz(row, c * 16));
            const float inv = s_inv[row];
            float4 o0, o1;
            float2 f;
            f = __half22float2(*reinterpret_cast<__half2*>(&pv4.x));
            o0.x = f.x * inv;  o0.y = f.y * inv;
            f = __half22float2(*reinterpret_cast<__half2*>(&pv4.y));
            o0.z = f.x * inv;  o0.w = f.y * inv;
            f = __half22float2(*reinterpret_cast<__half2*>(&pv4.z));
            o1.x = f.x * inv;  o1.y = f.y * inv;
            f = __half22float2(*reinterpret_cast<__half2*>(&pv4.w));
            o1.z = f.x * inv;  o1.w = f.y * inv;
            float* dst = Aout + (size_t)(m0 + row) * S_ + k0 + c * 8;
            *reinterpret_cast<float4*>(dst)     = o0;
            *reinterpret_cast<float4*>(dst + 4) = o1;
        }

        compute_stage1(cb + OFF1_A, cb + OFF1_B, wm, wn, lane, acc);
        __syncthreads();
    }

    // epilogue: fp32 partial ctx scaled by inv
    const int b = bh >> 4, h = bh & 15;
    float* dst = g_ctxp + (size_t)kz * BS_ * D_;
#pragma unroll
    for (int mt = 0; mt < 2; mt++)
#pragma unroll
        for (int nt = 0; nt < 4; nt++) {
            const int c = wn * 32 + nt * 8 + 2 * (lane & 3);
#pragma unroll
            for (int half = 0; half < 2; half++) {
                const int rowl = wm * 32 + mt * 16 + (lane >> 2) + half * 8;
                const float inv = s_inv[rowl];
                const int s = m0 + rowl;
                float2 v = { acc[mt][nt][half * 2] * inv,
                             acc[mt][nt][half * 2 + 1] * inv };
                *reinterpret_cast<float2*>(&dst[(size_t)(b * S_ + s) * D_ + h * DK_ + c]) = v;
            }
        }
}

// ---------------- ctx reduce: sum 4 partials -> single fp16 --------------------
__global__ void ctx_reduce()
{
    const size_t i = ((size_t)blockIdx.x * 256 + threadIdx.x) * 2;
    float2 s = {0.f, 0.f};
#pragma unroll
    for (int p = 0; p < 4; p++) {
        float2 v = *reinterpret_cast<const float2*>(&g_ctxp[(size_t)p * BS_ * D_ + i]);
        s.x += v.x; s.y += v.y;
    }
    *reinterpret_cast<unsigned*>(g_c1 + i) = pack_h2(s.x, s.y);
}

// =============================================================================
// Kernel 4: out = ctx @ Wo^T + bo (A single)
// =============================================================================
__global__ __launch_bounds__(256, 2) void oproj_gemm(const float* __restrict__ bo,
                                                     float* __restrict__ out)
{
    extern __shared__ char sm[];
    const unsigned sb = smem_u32(sm);
    const int m0 = blockIdx.y * 128, n0 = blockIdx.x * 64;
    const int tid = threadIdx.x, lane = tid & 31, wid = tid >> 5;
    const int wm = wid >> 1, wn = wid & 1;
    float acc[2][4][4] = {};

    cpA1_tile(sb + OFF1_A, g_c1, D_, m0, 0, tid);
    cpB1_tile(sb + OFF1_B, g_wo, D_, n0, 0, tid);
    CP_COMMIT;
    for (int it = 0; it < 16; it++) {
        const unsigned cb = sb + (it & 1) * STAGE1_BYTES;
        if (it + 1 < 16) {
            const unsigned nb = sb + ((it + 1) & 1) * STAGE1_BYTES;
            cpA1_tile(nb + OFF1_A, g_c1, D_, m0, (it + 1) * 64, tid);
            cpB1_tile(nb + OFF1_B, g_wo, D_, n0, (it + 1) * 64, tid);
            CP_COMMIT;
            CP_WAIT1;
        } else { CP_WAIT0; }
        __syncthreads();
        compute_stage1(cb + OFF1_A, cb + OFF1_B, wm, wn, lane, acc);
        __syncthreads();
    }

    const int tm0 = m0 + wm * 32, tn0 = n0 + wn * 32;
#pragma unroll
    for (int mt = 0; mt < 2; mt++)
#pragma unroll
        for (int nt = 0; nt < 4; nt++) {
            const int c = tn0 + nt * 8 + 2 * (lane & 3);
            const float b0 = bo[c], b1 = bo[c + 1];
#pragma unroll
            for (int half = 0; half < 2; half++) {
                const int m = tm0 + mt * 16 + (lane >> 2) + half * 8;
                float2 v = { acc[mt][nt][half * 2] + b0,
                             acc[mt][nt][half * 2 + 1] + b1 };
                *reinterpret_cast<float2*>(out + (size_t)m * D_ + c) = v;
            }
        }
}

// =============================================================================
extern "C" void kernel_launch(void* const* d_in, const int* in_sizes, int n_in,
                              void* d_out, int out_size)
{
    const float* x  = (const float*)d_in[0];
    const float* wq = (const float*)d_in[1];
    const float* bq = (const float*)d_in[2];
    const float* wk = (const float*)d_in[3];
    const float* bk = (const float*)d_in[4];
    const float* wv = (const float*)d_in[5];
    const float* bv = (const float*)d_in[6];
    const float* wo = (const float*)d_in[7];
    const float* bo = (const float*)d_in[8];

    float* out = (float*)d_out;
    const long long OUT_E  = (long long)BS_ * D_;
    const long long ATTN_E = (long long)NBH_ * S_ * S_;
    float* attn = ((long long)out_size >= OUT_E + ATTN_E) ? (out + OUT_E) : nullptr;

    static bool attr_done = false;
    if (!attr_done) {
        cudaFuncSetAttribute(qkv_gemm,    cudaFuncAttributeMaxDynamicSharedMemorySize, 2 * STAGE_BYTES);
        cudaFuncSetAttribute(pv_gemm,     cudaFuncAttributeMaxDynamicSharedMemorySize, 2 * STAGE1_BYTES);
        cudaFuncSetAttribute(oproj_gemm,  cudaFuncAttributeMaxDynamicSharedMemorySize, 2 * STAGE1_BYTES);
        cudaFuncSetAttribute(scores_gemm, cudaFuncAttributeMaxDynamicSharedMemorySize, STAGE_BYTES);
        attr_done = true;
    }

    // 0. precision splits / casts
    prep_kernel<<<16384, 256>>>(x, wq, wk, wv, wo);

    // 1. QKV projection (fused N=3072), Q pre-scaled by 1/8
    qkv_gemm<<<dim3(3 * D_ / 64, BS_ / 128), 256, 2 * STAGE_BYTES>>>(bq, bk, bv);

    // 2. P = exp(QK^T/8) single fp16 + deterministic partial row sums
    scores_gemm<<<dim3(S_ / 64, S_ / 128, NBH_), 256, STAGE_BYTES>>>();

    // 3. inverse row sums
    inv_kernel<<<NBH_ * S_ / 256, 256>>>();

    // 4. pv split-K=4: partial ctx + normalized attn fp32 output
    pv_gemm<<<dim3(4, S_ / 128, NBH_), 256, 2 * STAGE1_BYTES>>>(attn);

    // 5. reduce ctx partials -> single fp16
    ctx_reduce<<<BS_ * D_ / 512, 256>>>();

    // 6. out projection
    oproj_gemm<<<dim3(D_ / 64, BS_ / 128), 256, 2 * STAGE1_BYTES>>>(bo, out);
}

// round 9
// speedup vs baseline: 1.5886x; 1.1190x over previous
#include <cuda_runtime.h>
#include <cuda_fp16.h>

#define B_   2
#define S_   2048
#define D_   1024
#define H_   16
#define DK_  64
#define BS_  (B_*S_)            // 4096
#define NBH_ (B_*H_)            // 32

// ---------------- device scratch (no allocations allowed) -------------------
__device__ __half g_x1[BS_ * D_];                         // x fp16 single (A)
__device__ __half g_w3[3 * D_ * D_];                      // wq|wk|wv single (B)
__device__ __half g_wo[D_ * D_];                          // wo single (B)
__device__ __half g_qh[NBH_ * S_ * DK_], g_ql[NBH_ * S_ * DK_]; // Q hi/lo (A)
__device__ __half g_k1[NBH_ * S_ * DK_];                  // K single (B)
__device__ __half g_vt[NBH_ * DK_ * S_];                  // V^T single (B) [bh][d][s]
__device__ __half g_c1[BS_ * D_];                         // ctx single (A)
__device__ __half g_p1[(size_t)NBH_ * S_ * S_];           // exp(scores) single (A)
__device__ float g_rsum_part[64][NBH_ * S_];              // deterministic partials
__device__ float g_inv[NBH_ * S_];                        // 1/rowsum
__device__ float g_ctxp[4 * BS_ * D_];                    // split-K ctx partials
__device__ float g_attn_fb[(size_t)NBH_ * S_ * S_];       // fallback

// ---------------- smem layouts -------------------------------------------------
// hi/lo-A GEMM (scores): A hi 16K + A lo 16K + B 8K
#define OFF_AH 0
#define OFF_AL 16384
#define OFF_B  32768
#define STAGE_BYTES 40960
// single-A GEMMs (qkv, pv, oproj): A 16K + B 8K
#define OFF1_A 0
#define OFF1_B 16384
#define STAGE1_BYTES 24576

// ---------------- helpers ----------------------------------------------------
__device__ __forceinline__ unsigned smem_u32(const void* p) {
    return (unsigned)__cvta_generic_to_shared(p);
}
__device__ __forceinline__ void ldsm4(unsigned r[4], unsigned addr) {
    asm volatile("ldmatrix.sync.aligned.m8n8.x4.shared.b16 {%0,%1,%2,%3}, [%4];\n"
                 : "=r"(r[0]), "=r"(r[1]), "=r"(r[2]), "=r"(r[3]) : "r"(addr));
}
__device__ __forceinline__ void mma16816h(float (&d)[4], const unsigned a[4],
                                          unsigned b0, unsigned b1) {
    asm volatile(
        "mma.sync.aligned.m16n8k16.row.col.f32.f16.f16.f32 "
        "{%0,%1,%2,%3}, {%4,%5,%6,%7}, {%8,%9}, {%0,%1,%2,%3};\n"
        : "+f"(d[0]), "+f"(d[1]), "+f"(d[2]), "+f"(d[3])
        : "r"(a[0]), "r"(a[1]), "r"(a[2]), "r"(a[3]), "r"(b0), "r"(b1));
}
__device__ __forceinline__ void split2h(float x, float y, unsigned &h, unsigned &l) {
    __half2 hv = __floats2half2_rn(x, y);
    float rx = x - __low2float(hv);
    float ry = y - __high2float(hv);
    __half2 lv = __floats2half2_rn(rx, ry);
    h = *reinterpret_cast<unsigned*>(&hv);
    l = *reinterpret_cast<unsigned*>(&lv);
}
__device__ __forceinline__ unsigned pack_h2(float x, float y) {
    __half2 hv = __floats2half2_rn(x, y);
    return *reinterpret_cast<unsigned*>(&hv);
}
__device__ __forceinline__ unsigned swz(int row, int kb) {
    return (unsigned)(row * 128 + (kb ^ ((row & 7) << 4)));
}
__device__ __forceinline__ void cp16(unsigned dst, const void* src) {
    asm volatile("cp.async.cg.shared.global [%0], [%1], 16;\n" :: "r"(dst), "l"(src));
}
#define CP_COMMIT asm volatile("cp.async.commit_group;\n" ::: "memory")
#define CP_WAIT1  asm volatile("cp.async.wait_group 1;\n" ::: "memory")
#define CP_WAIT0  asm volatile("cp.async.wait_group 0;\n" ::: "memory")

// ---------------- cp.async tile staging ---------------------------------------
__device__ __forceinline__ void cpA_tile(unsigned AH, unsigned AL,
    const __half* __restrict__ Ah, const __half* __restrict__ Al,
    int ld, int m0, int k0, int tid)
{
#pragma unroll
    for (int j = 0; j < 4; j++) {
        int id = tid + j * 256, row = id >> 3, c = id & 7;
        size_t g = (size_t)(m0 + row) * ld + k0 + c * 8;
        unsigned o = swz(row, c * 16);
        cp16(AH + o, Ah + g);
        cp16(AL + o, Al + g);
    }
}
__device__ __forceinline__ void cpA1_tile(unsigned Ab,
    const __half* __restrict__ Ap, int ld, int m0, int k0, int tid)
{
#pragma unroll
    for (int j = 0; j < 4; j++) {
        int id = tid + j * 256, row = id >> 3, c = id & 7;
        size_t g = (size_t)(m0 + row) * ld + k0 + c * 8;
        cp16(Ab + swz(row, c * 16), Ap + g);
    }
}
__device__ __forceinline__ void cpB1_tile(unsigned Bb,
    const __half* __restrict__ Bp, int ld, int n0, int k0, int tid)
{
#pragma unroll
    for (int j = 0; j < 2; j++) {
        int id = tid + j * 256, row = id >> 3, c = id & 7;
        size_t g = (size_t)(n0 + row) * ld + k0 + c * 8;
        cp16(Bb + swz(row, c * 16), Bp + g);
    }
}

// ---------------- compute: A hi/lo (2 MMA) ------------------------------------
__device__ __forceinline__ void compute_stage(unsigned aBase, unsigned bBase,
                                              int wm, int wn, int lane,
                                              float acc[2][4][4])
{
    const int arow0 = wm * 32 + (lane & 15);
    const int akh   = ((lane >> 4) & 1) * 16;
    const int brow0 = wn * 32 + ((lane >> 4) & 1) * 8 + (lane & 7);
    const int bkh   = ((lane >> 3) & 1) * 16;
#pragma unroll
    for (int ks = 0; ks < 4; ks++) {
        unsigned ah[2][4], al[2][4], bm[2][4];
#pragma unroll
        for (int mt = 0; mt < 2; mt++) {
            unsigned off = swz(arow0 + mt * 16, ks * 32 + akh);
            ldsm4(ah[mt], aBase + off);
            ldsm4(al[mt], aBase + 16384 + off);
        }
#pragma unroll
        for (int p = 0; p < 2; p++) {
            unsigned off = swz(brow0 + p * 16, ks * 32 + bkh);
            ldsm4(bm[p], bBase + off);
        }
#pragma unroll
        for (int mt = 0; mt < 2; mt++)
#pragma unroll
            for (int nt = 0; nt < 4; nt++) {
                unsigned b0 = bm[nt >> 1][(nt & 1) * 2], b1 = bm[nt >> 1][(nt & 1) * 2 + 1];
                mma16816h(acc[mt][nt], ah[mt], b0, b1);
                mma16816h(acc[mt][nt], al[mt], b0, b1);
            }
    }
}
// ---------------- compute: A single (1 MMA) ------------------------------------
__device__ __forceinline__ void compute_stage1(unsigned aBase, unsigned bBase,
                                               int wm, int wn, int lane,
                                               float acc[2][4][4])
{
    const int arow0 = wm * 32 + (lane & 15);
    const int akh   = ((lane >> 4) & 1) * 16;
    const int brow0 = wn * 32 + ((lane >> 4) & 1) * 8 + (lane & 7);
    const int bkh   = ((lane >> 3) & 1) * 16;
#pragma unroll
    for (int ks = 0; ks < 4; ks++) {
        unsigned am[2][4], bm[2][4];
#pragma unroll
        for (int mt = 0; mt < 2; mt++)
            ldsm4(am[mt], aBase + swz(arow0 + mt * 16, ks * 32 + akh));
#pragma unroll
        for (int p = 0; p < 2; p++)
            ldsm4(bm[p], bBase + swz(brow0 + p * 16, ks * 32 + bkh));
#pragma unroll
        for (int mt = 0; mt < 2; mt++)
#pragma unroll
            for (int nt = 0; nt < 4; nt++)
                mma16816h(acc[mt][nt], am[mt],
                          bm[nt >> 1][(nt & 1) * 2], bm[nt >> 1][(nt & 1) * 2 + 1]);
    }
}

// ---------------- prep: fp32 -> fp16 casts --------------------------------------
__global__ void prep_kernel(const float* __restrict__ x,
                            const float* __restrict__ wq,
                            const float* __restrict__ wk,
                            const float* __restrict__ wv,
                            const float* __restrict__ wo)
{
    const int bid = blockIdx.x, tid = threadIdx.x;
    const float* src;
    __half* dst;
    int base;
    if (bid < 8192)       { src = x;  dst = g_x1;             base = 0;     }
    else if (bid < 10240) { src = wq; dst = g_w3;             base = 8192;  }
    else if (bid < 12288) { src = wk; dst = g_w3 + D_*D_;     base = 10240; }
    else if (bid < 14336) { src = wv; dst = g_w3 + 2*D_*D_;   base = 12288; }
    else                  { src = wo; dst = g_wo;             base = 14336; }
    int i = ((bid - base) * 256 + tid) * 2;
    *reinterpret_cast<unsigned*>(dst + i) = pack_h2(src[i], src[i + 1]);
}

// =============================================================================
// Kernel 1: fused QKV projection (single-A); Q 1/8 hi/lo; K single; V^T single
// =============================================================================
__global__ __launch_bounds__(256, 2) void qkv_gemm(const float* __restrict__ bq,
                                                   const float* __restrict__ bk,
                                                   const float* __restrict__ bv)
{
    extern __shared__ char sm[];
    const unsigned sb = smem_u32(sm);
    const int m0 = blockIdx.y * 128, n0 = blockIdx.x * 64;
    const int tid = threadIdx.x, lane = tid & 31, wid = tid >> 5;
    const int wm = wid >> 1, wn = wid & 1;
    float acc[2][4][4] = {};

    cpA1_tile(sb + OFF1_A, g_x1, D_, m0, 0, tid);
    cpB1_tile(sb + OFF1_B, g_w3, D_, n0, 0, tid);
    CP_COMMIT;
    for (int it = 0; it < 16; it++) {
        const unsigned cb = sb + (it & 1) * STAGE1_BYTES;
        if (it + 1 < 16) {
            const unsigned nb = sb + ((it + 1) & 1) * STAGE1_BYTES;
            cpA1_tile(nb + OFF1_A, g_x1, D_, m0, (it + 1) * 64, tid);
            cpB1_tile(nb + OFF1_B, g_w3, D_, n0, (it + 1) * 64, tid);
            CP_COMMIT;
            CP_WAIT1;
        } else { CP_WAIT0; }
        __syncthreads();
        compute_stage1(cb + OFF1_A, cb + OFF1_B, wm, wn, lane, acc);
        __syncthreads();
    }

    const int reg = n0 >> 10;                 // 0=Q,1=K,2=V
    const int h   = (n0 & 1023) >> 6;
    const float* bp = (reg == 0) ? bq : (reg == 1) ? bk : bv;
    const float scale = (reg == 0) ? 0.125f : 1.0f;
    const int tm0 = m0 + wm * 32, tn0 = n0 + wn * 32;

#pragma unroll
    for (int mt = 0; mt < 2; mt++)
#pragma unroll
        for (int nt = 0; nt < 4; nt++) {
            const int c  = tn0 + nt * 8 + 2 * (lane & 3);
            const int d  = c & 63;
            const float bias0 = bp[c & 1023], bias1 = bp[(c & 1023) + 1];
#pragma unroll
            for (int half = 0; half < 2; half++) {
                const int m = tm0 + mt * 16 + (lane >> 2) + half * 8;
                const float v0 = (acc[mt][nt][half * 2]     + bias0) * scale;
                const float v1 = (acc[mt][nt][half * 2 + 1] + bias1) * scale;
                const int b = m >> 11, s = m & 2047;
                const size_t bh = (size_t)(b * H_ + h);
                if (reg == 0) {
                    unsigned hh, ll;
                    split2h(v0, v1, hh, ll);
                    size_t idx = (bh * S_ + s) * DK_ + d;
                    *reinterpret_cast<unsigned*>(g_qh + idx) = hh;
                    *reinterpret_cast<unsigned*>(g_ql + idx) = ll;
                } else if (reg == 1) {
                    size_t idx = (bh * S_ + s) * DK_ + d;
                    *reinterpret_cast<unsigned*>(g_k1 + idx) = pack_h2(v0, v1);
                } else {
                    size_t i0 = (bh * DK_ + d) * S_ + s;
                    g_vt[i0]      = __float2half(v0);
                    g_vt[i0 + S_] = __float2half(v1);
                }
            }
        }
}

// =============================================================================
// Kernel 2: P = exp(QK^T/8) single fp16 + deterministic partial row sums
// (A = Q hi/lo for score precision)
// =============================================================================
__global__ __launch_bounds__(256) void scores_gemm()
{
    extern __shared__ char sm[];
    const unsigned sb = smem_u32(sm);
    const int bh = blockIdx.z;
    const int m0 = blockIdx.y * 128, n0 = blockIdx.x * 64;
    const int tid = threadIdx.x, lane = tid & 31, wid = tid >> 5;
    const int wm = wid >> 1, wn = wid & 1;

    const __half* Ah = g_qh + (size_t)bh * S_ * DK_;
    const __half* Al = g_ql + (size_t)bh * S_ * DK_;
    const __half* Bp = g_k1 + (size_t)bh * S_ * DK_;

    float acc[2][4][4] = {};
    cpA_tile(sb + OFF_AH, sb + OFF_AL, Ah, Al, DK_, m0, 0, tid);
    cpB1_tile(sb + OFF_B, Bp, DK_, n0, 0, tid);
    CP_COMMIT;
    CP_WAIT0;
    __syncthreads();
    compute_stage(sb + OFF_AH, sb + OFF_B, wm, wn, lane, acc);

    __half* Pp = g_p1 + (size_t)bh * S_ * S_;
    const int tm0 = m0 + wm * 32, tn0 = n0 + wn * 32;
    float rpart[2][2] = {};
#pragma unroll
    for (int mt = 0; mt < 2; mt++)
#pragma unroll
        for (int nt = 0; nt < 4; nt++) {
            const int c = tn0 + nt * 8 + 2 * (lane & 3);
#pragma unroll
            for (int half = 0; half < 2; half++) {
                const int m = tm0 + mt * 16 + (lane >> 2) + half * 8;
                const float e0 = __expf(acc[mt][nt][half * 2]);
                const float e1 = __expf(acc[mt][nt][half * 2 + 1]);
                *reinterpret_cast<unsigned*>(Pp + (size_t)m * S_ + c) = pack_h2(e0, e1);
                rpart[mt][half] += e0 + e1;
            }
        }

    const int slot = blockIdx.x * 2 + wn;
#pragma unroll
    for (int mt = 0; mt < 2; mt++)
#pragma unroll
        for (int half = 0; half < 2; half++) {
            float v = rpart[mt][half];
            v += __shfl_xor_sync(0xffffffffu, v, 1);
            v += __shfl_xor_sync(0xffffffffu, v, 2);
            if ((lane & 3) == 0) {
                const int m = tm0 + mt * 16 + (lane >> 2) + half * 8;
                g_rsum_part[slot][(size_t)bh * S_ + m] = v;
            }
        }
}

// ---------------- inv_kernel: 1/rowsum from 64 partials ------------------------
__global__ void inv_kernel()
{
    const int r = blockIdx.x * 256 + threadIdx.x;   // 65536 rows
    float s = 0.f;
#pragma unroll
    for (int p = 0; p < 64; p++) s += g_rsum_part[p][r];
    g_inv[r] = 1.0f / s;
}

// =============================================================================
// Kernel 3: pv split-K=4: partial ctx = (P·V)·inv ; writes normalized attn fp32
// =============================================================================
__global__ __launch_bounds__(256, 2) void pv_gemm(float* __restrict__ attn_arg)
{
    extern __shared__ char sm[];
    __shared__ float s_inv[128];
    const unsigned sb = smem_u32(sm);
    float* attn = attn_arg ? attn_arg : g_attn_fb;
    const int kz = blockIdx.x, bh = blockIdx.z;
    const int m0 = blockIdx.y * 128;
    const int tid = threadIdx.x, lane = tid & 31, wid = tid >> 5;
    const int wm = wid >> 1, wn = wid & 1;

    if (tid < 128) s_inv[tid] = g_inv[(size_t)bh * S_ + m0 + tid];

    const __half* Pp = g_p1 + (size_t)bh * S_ * S_;
    const __half* Vp = g_vt + (size_t)bh * DK_ * S_;
    float* Aout = attn + (size_t)bh * S_ * S_;

    float acc[2][4][4] = {};
    const int kbase = kz * 512;

    cpA1_tile(sb + OFF1_A, Pp, S_, m0, kbase, tid);
    cpB1_tile(sb + OFF1_B, Vp, S_, 0, kbase, tid);
    CP_COMMIT;
    for (int it = 0; it < 8; it++) {
        const int cur = it & 1;
        const unsigned cb = sb + cur * STAGE1_BYTES;
        const int k0 = kbase + it * 64;
        if (it + 1 < 8) {
            const unsigned nb = sb + (1 - cur) * STAGE1_BYTES;
            cpA1_tile(nb + OFF1_A, Pp, S_, m0, k0 + 64, tid);
            cpB1_tile(nb + OFF1_B, Vp, S_, 0, k0 + 64, tid);
            CP_COMMIT;
            CP_WAIT1;
        } else { CP_WAIT0; }
        __syncthreads();

        // write normalized attn fp32 from this stage's A tile (each elem once)
        const char* cbc = sm + cur * STAGE1_BYTES;
#pragma unroll
        for (int j = 0; j < 4; j++) {
            int id = tid + j * 256, row = id >> 3, c = id & 7;
            uint4 pv4 = *reinterpret_cast<const uint4*>(cbc + OFF1_A + swz(row, c * 16));
            const float inv = s_inv[row];
            float4 o0, o1;
            float2 f;
            f = __half22float2(*reinterpret_cast<__half2*>(&pv4.x));
            o0.x = f.x * inv;  o0.y = f.y * inv;
            f = __half22float2(*reinterpret_cast<__half2*>(&pv4.y));
            o0.z = f.x * inv;  o0.w = f.y * inv;
            f = __half22float2(*reinterpret_cast<__half2*>(&pv4.z));
            o1.x = f.x * inv;  o1.y = f.y * inv;
            f = __half22float2(*reinterpret_cast<__half2*>(&pv4.w));
            o1.z = f.x * inv;  o1.w = f.y * inv;
            float* dst = Aout + (size_t)(m0 + row) * S_ + k0 + c * 8;
            *reinterpret_cast<float4*>(dst)     = o0;
            *reinterpret_cast<float4*>(dst + 4) = o1;
        }

        compute_stage1(cb + OFF1_A, cb + OFF1_B, wm, wn, lane, acc);
        __syncthreads();
    }

    // epilogue: fp32 partial ctx scaled by inv
    const int b = bh >> 4, h = bh & 15;
    float* dst = g_ctxp + (size_t)kz * BS_ * D_;
#pragma unroll
    for (int mt = 0; mt < 2; mt++)
#pragma unroll
        for (int nt = 0; nt < 4; nt++) {
            const int c = wn * 32 + nt * 8 + 2 * (lane & 3);
#pragma unroll
            for (int half = 0; half < 2; half++) {
                const int rowl = wm * 32 + mt * 16 + (lane >> 2) + half * 8;
                const float inv = s_inv[rowl];
                const int s = m0 + rowl;
                float2 v = { acc[mt][nt][half * 2] * inv,
                             acc[mt][nt][half * 2 + 1] * inv };
                *reinterpret_cast<float2*>(&dst[(size_t)(b * S_ + s) * D_ + h * DK_ + c]) = v;
            }
        }
}

// ---------------- ctx reduce: sum 4 partials -> single fp16 --------------------
__global__ void ctx_reduce()
{
    const size_t i = ((size_t)blockIdx.x * 256 + threadIdx.x) * 2;
    float2 s = {0.f, 0.f};
#pragma unroll
    for (int p = 0; p < 4; p++) {
        float2 v = *reinterpret_cast<const float2*>(&g_ctxp[(size_t)p * BS_ * D_ + i]);
        s.x += v.x; s.y += v.y;
    }
    *reinterpret_cast<unsigned*>(g_c1 + i) = pack_h2(s.x, s.y);
}

// =============================================================================
// Kernel 4: out = ctx @ Wo^T + bo (A single)
// =============================================================================
__global__ __launch_bounds__(256, 2) void oproj_gemm(const float* __restrict__ bo,
                                                     float* __restrict__ out)
{
    extern __shared__ char sm[];
    const unsigned sb = smem_u32(sm);
    const int m0 = blockIdx.y * 128, n0 = blockIdx.x * 64;
    const int tid = threadIdx.x, lane = tid & 31, wid = tid >> 5;
    const int wm = wid >> 1, wn = wid & 1;
    float acc[2][4][4] = {};

    cpA1_tile(sb + OFF1_A, g_c1, D_, m0, 0, tid);
    cpB1_tile(sb + OFF1_B, g_wo, D_, n0, 0, tid);
    CP_COMMIT;
    for (int it = 0; it < 16; it++) {
        const unsigned cb = sb + (it & 1) * STAGE1_BYTES;
        if (it + 1 < 16) {
            const unsigned nb = sb + ((it + 1) & 1) * STAGE1_BYTES;
            cpA1_tile(nb + OFF1_A, g_c1, D_, m0, (it + 1) * 64, tid);
            cpB1_tile(nb + OFF1_B, g_wo, D_, n0, (it + 1) * 64, tid);
            CP_COMMIT;
            CP_WAIT1;
        } else { CP_WAIT0; }
        __syncthreads();
        compute_stage1(cb + OFF1_A, cb + OFF1_B, wm, wn, lane, acc);
        __syncthreads();
    }

    const int tm0 = m0 + wm * 32, tn0 = n0 + wn * 32;
#pragma unroll
    for (int mt = 0; mt < 2; mt++)
#pragma unroll
        for (int nt = 0; nt < 4; nt++) {
            const int c = tn0 + nt * 8 + 2 * (lane & 3);
            const float b0 = bo[c], b1 = bo[c + 1];
#pragma unroll
            for (int half = 0; half < 2; half++) {
                const int m = tm0 + mt * 16 + (lane >> 2) + half * 8;
                float2 v = { acc[mt][nt][half * 2] + b0,
                             acc[mt][nt][half * 2 + 1] + b1 };
                *reinterpret_cast<float2*>(out + (size_t)m * D_ + c) = v;
            }
        }
}

// =============================================================================
extern "C" void kernel_launch(void* const* d_in, const int* in_sizes, int n_in,
                              void* d_out, int out_size)
{
    const float* x  = (const float*)d_in[0];
    const float* wq = (const float*)d_in[1];
    const float* bq = (const float*)d_in[2];
    const float* wk = (const float*)d_in[3];
    const float* bk = (const float*)d_in[4];
    const float* wv = (const float*)d_in[5];
    const float* bv = (const float*)d_in[6];
    const float* wo = (const float*)d_in[7];
    const float* bo = (const float*)d_in[8];

    float* out = (float*)d_out;
    const long long OUT_E  = (long long)BS_ * D_;
    const long long ATTN_E = (long long)NBH_ * S_ * S_;
    float* attn = ((long long)out_size >= OUT_E + ATTN_E) ? (out + OUT_E) : nullptr;

    static bool attr_done = false;
    if (!attr_done) {
        cudaFuncSetAttribute(qkv_gemm,    cudaFuncAttributeMaxDynamicSharedMemorySize, 2 * STAGE1_BYTES);
        cudaFuncSetAttribute(pv_gemm,     cudaFuncAttributeMaxDynamicSharedMemorySize, 2 * STAGE1_BYTES);
        cudaFuncSetAttribute(oproj_gemm,  cudaFuncAttributeMaxDynamicSharedMemorySize, 2 * STAGE1_BYTES);
        cudaFuncSetAttribute(scores_gemm, cudaFuncAttributeMaxDynamicSharedMemorySize, STAGE_BYTES);
        attr_done = true;
    }

    // 0. precision casts
    prep_kernel<<<16384, 256>>>(x, wq, wk, wv, wo);

    // 1. QKV projection (single-A), Q pre-scaled by 1/8
    qkv_gemm<<<dim3(3 * D_ / 64, BS_ / 128), 256, 2 * STAGE1_BYTES>>>(bq, bk, bv);

    // 2. P = exp(QK^T/8) single fp16 + deterministic partial row sums
    scores_gemm<<<dim3(S_ / 64, S_ / 128, NBH_), 256, STAGE_BYTES>>>();

    // 3. inverse row sums
    inv_kernel<<<NBH_ * S_ / 256, 256>>>();

    // 4. pv split-K=4: partial ctx + normalized attn fp32 output
    pv_gemm<<<dim3(4, S_ / 128, NBH_), 256, 2 * STAGE1_BYTES>>>(attn);

    // 5. reduce ctx partials -> single fp16
    ctx_reduce<<<BS_ * D_ / 512, 256>>>();

    // 6. out projection
    oproj_gemm<<<dim3(D_ / 64, BS_ / 128), 256, 2 * STAGE1_BYTES>>>(bo, out);
}

// round 10
// speedup vs baseline: 1.7201x; 1.0827x over previous
#include <cuda_runtime.h>
#include <cuda_fp16.h>

#define B_   2
#define S_   2048
#define D_   1024
#define H_   16
#define DK_  64
#define BS_  (B_*S_)            // 4096
#define NBH_ (B_*H_)            // 32

// ---------------- device scratch (no allocations allowed) -------------------
__device__ __half g_x1[BS_ * D_];                         // x fp16 (A)
__device__ __half g_w3[3 * D_ * D_];                      // wq|wk|wv (B)
__device__ __half g_wo[D_ * D_];                          // wo (B)
__device__ __half g_q1[NBH_ * S_ * DK_];                  // Q/8 fp16 (A)
__device__ __half g_k1[NBH_ * S_ * DK_];                  // K fp16 (B)
__device__ __half g_vt[NBH_ * DK_ * S_];                  // V^T fp16 (B) [bh][d][s]
__device__ __half g_c1[BS_ * D_];                         // ctx fp16 (A)
__device__ __half g_p1[(size_t)NBH_ * S_ * S_];           // exp(scores) fp16 (A)
__device__ float g_rsum_part[64][NBH_ * S_];              // deterministic partials
__device__ float g_inv[NBH_ * S_];                        // 1/rowsum
__device__ float g_ctxp[4 * BS_ * D_];                    // split-K ctx partials
__device__ float g_attn_fb[(size_t)NBH_ * S_ * S_];       // fallback

// ---------------- smem layout (single-A, per stage): A 16K + B 8K ------------
#define OFF1_A 0
#define OFF1_B 16384
#define STAGE1_BYTES 24576

// ---------------- helpers ----------------------------------------------------
__device__ __forceinline__ unsigned smem_u32(const void* p) {
    return (unsigned)__cvta_generic_to_shared(p);
}
__device__ __forceinline__ void ldsm4(unsigned r[4], unsigned addr) {
    asm volatile("ldmatrix.sync.aligned.m8n8.x4.shared.b16 {%0,%1,%2,%3}, [%4];\n"
                 : "=r"(r[0]), "=r"(r[1]), "=r"(r[2]), "=r"(r[3]) : "r"(addr));
}
__device__ __forceinline__ void mma16816h(float (&d)[4], const unsigned a[4],
                                          unsigned b0, unsigned b1) {
    asm volatile(
        "mma.sync.aligned.m16n8k16.row.col.f32.f16.f16.f32 "
        "{%0,%1,%2,%3}, {%4,%5,%6,%7}, {%8,%9}, {%0,%1,%2,%3};\n"
        : "+f"(d[0]), "+f"(d[1]), "+f"(d[2]), "+f"(d[3])
        : "r"(a[0]), "r"(a[1]), "r"(a[2]), "r"(a[3]), "r"(b0), "r"(b1));
}
__device__ __forceinline__ unsigned pack_h2(float x, float y) {
    __half2 hv = __floats2half2_rn(x, y);
    return *reinterpret_cast<unsigned*>(&hv);
}
__device__ __forceinline__ unsigned swz(int row, int kb) {
    return (unsigned)(row * 128 + (kb ^ ((row & 7) << 4)));
}
__device__ __forceinline__ void cp16(unsigned dst, const void* src) {
    asm volatile("cp.async.cg.shared.global [%0], [%1], 16;\n" :: "r"(dst), "l"(src));
}
#define CP_COMMIT asm volatile("cp.async.commit_group;\n" ::: "memory")
#define CP_WAIT1  asm volatile("cp.async.wait_group 1;\n" ::: "memory")
#define CP_WAIT0  asm volatile("cp.async.wait_group 0;\n" ::: "memory")

// ---------------- cp.async tile staging ---------------------------------------
__device__ __forceinline__ void cpA1_tile(unsigned Ab,
    const __half* __restrict__ Ap, int ld, int m0, int k0, int tid)
{
#pragma unroll
    for (int j = 0; j < 4; j++) {
        int id = tid + j * 256, row = id >> 3, c = id & 7;
        size_t g = (size_t)(m0 + row) * ld + k0 + c * 8;
        cp16(Ab + swz(row, c * 16), Ap + g);
    }
}
__device__ __forceinline__ void cpB1_tile(unsigned Bb,
    const __half* __restrict__ Bp, int ld, int n0, int k0, int tid)
{
#pragma unroll
    for (int j = 0; j < 2; j++) {
        int id = tid + j * 256, row = id >> 3, c = id & 7;
        size_t g = (size_t)(n0 + row) * ld + k0 + c * 8;
        cp16(Bb + swz(row, c * 16), Bp + g);
    }
}

// ---------------- compute: A single (1 MMA per k-step) -------------------------
__device__ __forceinline__ void compute_stage1(unsigned aBase, unsigned bBase,
                                               int wm, int wn, int lane,
                                               float acc[2][4][4])
{
    const int arow0 = wm * 32 + (lane & 15);
    const int akh   = ((lane >> 4) & 1) * 16;
    const int brow0 = wn * 32 + ((lane >> 4) & 1) * 8 + (lane & 7);
    const int bkh   = ((lane >> 3) & 1) * 16;
#pragma unroll
    for (int ks = 0; ks < 4; ks++) {
        unsigned am[2][4], bm[2][4];
#pragma unroll
        for (int mt = 0; mt < 2; mt++)
            ldsm4(am[mt], aBase + swz(arow0 + mt * 16, ks * 32 + akh));
#pragma unroll
        for (int p = 0; p < 2; p++)
            ldsm4(bm[p], bBase + swz(brow0 + p * 16, ks * 32 + bkh));
#pragma unroll
        for (int mt = 0; mt < 2; mt++)
#pragma unroll
            for (int nt = 0; nt < 4; nt++)
                mma16816h(acc[mt][nt], am[mt],
                          bm[nt >> 1][(nt & 1) * 2], bm[nt >> 1][(nt & 1) * 2 + 1]);
    }
}

// ---------------- prep: fp32 -> fp16 casts --------------------------------------
__global__ void prep_kernel(const float* __restrict__ x,
                            const float* __restrict__ wq,
                            const float* __restrict__ wk,
                            const float* __restrict__ wv,
                            const float* __restrict__ wo)
{
    const int bid = blockIdx.x, tid = threadIdx.x;
    const float* src;
    __half* dst;
    int base;
    if (bid < 8192)       { src = x;  dst = g_x1;             base = 0;     }
    else if (bid < 10240) { src = wq; dst = g_w3;             base = 8192;  }
    else if (bid < 12288) { src = wk; dst = g_w3 + D_*D_;     base = 10240; }
    else if (bid < 14336) { src = wv; dst = g_w3 + 2*D_*D_;   base = 12288; }
    else                  { src = wo; dst = g_wo;             base = 14336; }
    int i = ((bid - base) * 256 + tid) * 2;
    *reinterpret_cast<unsigned*>(dst + i) = pack_h2(src[i], src[i + 1]);
}

// =============================================================================
// Kernel 1: fused QKV projection (single-A); Q 1/8 single; K single; V^T single
// =============================================================================
__global__ __launch_bounds__(256, 2) void qkv_gemm(const float* __restrict__ bq,
                                                   const float* __restrict__ bk,
                                                   const float* __restrict__ bv)
{
    extern __shared__ char sm[];
    const unsigned sb = smem_u32(sm);
    const int m0 = blockIdx.y * 128, n0 = blockIdx.x * 64;
    const int tid = threadIdx.x, lane = tid & 31, wid = tid >> 5;
    const int wm = wid >> 1, wn = wid & 1;
    float acc[2][4][4] = {};

    cpA1_tile(sb + OFF1_A, g_x1, D_, m0, 0, tid);
    cpB1_tile(sb + OFF1_B, g_w3, D_, n0, 0, tid);
    CP_COMMIT;
    for (int it = 0; it < 16; it++) {
        const unsigned cb = sb + (it & 1) * STAGE1_BYTES;
        if (it + 1 < 16) {
            const unsigned nb = sb + ((it + 1) & 1) * STAGE1_BYTES;
            cpA1_tile(nb + OFF1_A, g_x1, D_, m0, (it + 1) * 64, tid);
            cpB1_tile(nb + OFF1_B, g_w3, D_, n0, (it + 1) * 64, tid);
            CP_COMMIT;
            CP_WAIT1;
        } else { CP_WAIT0; }
        __syncthreads();
        compute_stage1(cb + OFF1_A, cb + OFF1_B, wm, wn, lane, acc);
        __syncthreads();
    }

    const int reg = n0 >> 10;                 // 0=Q,1=K,2=V
    const int h   = (n0 & 1023) >> 6;
    const float* bp = (reg == 0) ? bq : (reg == 1) ? bk : bv;
    const float scale = (reg == 0) ? 0.125f : 1.0f;
    __half* dQ = (reg == 0) ? g_q1 : g_k1;
    const int tm0 = m0 + wm * 32, tn0 = n0 + wn * 32;

#pragma unroll
    for (int mt = 0; mt < 2; mt++)
#pragma unroll
        for (int nt = 0; nt < 4; nt++) {
            const int c  = tn0 + nt * 8 + 2 * (lane & 3);
            const int d  = c & 63;
            const float bias0 = bp[c & 1023], bias1 = bp[(c & 1023) + 1];
#pragma unroll
            for (int half = 0; half < 2; half++) {
                const int m = tm0 + mt * 16 + (lane >> 2) + half * 8;
                const float v0 = (acc[mt][nt][half * 2]     + bias0) * scale;
                const float v1 = (acc[mt][nt][half * 2 + 1] + bias1) * scale;
                const int b = m >> 11, s = m & 2047;
                const size_t bh = (size_t)(b * H_ + h);
                if (reg < 2) {
                    size_t idx = (bh * S_ + s) * DK_ + d;
                    *reinterpret_cast<unsigned*>(dQ + idx) = pack_h2(v0, v1);
                } else {
                    size_t i0 = (bh * DK_ + d) * S_ + s;
                    g_vt[i0]      = __float2half(v0);
                    g_vt[i0 + S_] = __float2half(v1);
                }
            }
        }
}

// =============================================================================
// Kernel 2: P = exp(QK^T/8) single fp16 + deterministic partial row sums
// =============================================================================
__global__ __launch_bounds__(256) void scores_gemm()
{
    extern __shared__ char sm[];
    const unsigned sb = smem_u32(sm);
    const int bh = blockIdx.z;
    const int m0 = blockIdx.y * 128, n0 = blockIdx.x * 64;
    const int tid = threadIdx.x, lane = tid & 31, wid = tid >> 5;
    const int wm = wid >> 1, wn = wid & 1;

    const __half* Ap = g_q1 + (size_t)bh * S_ * DK_;
    const __half* Bp = g_k1 + (size_t)bh * S_ * DK_;

    float acc[2][4][4] = {};
    cpA1_tile(sb + OFF1_A, Ap, DK_, m0, 0, tid);
    cpB1_tile(sb + OFF1_B, Bp, DK_, n0, 0, tid);
    CP_COMMIT;
    CP_WAIT0;
    __syncthreads();
    compute_stage1(sb + OFF1_A, sb + OFF1_B, wm, wn, lane, acc);

    __half* Pp = g_p1 + (size_t)bh * S_ * S_;
    const int tm0 = m0 + wm * 32, tn0 = n0 + wn * 32;
    float rpart[2][2] = {};
#pragma unroll
    for (int mt = 0; mt < 2; mt++)
#pragma unroll
        for (int nt = 0; nt < 4; nt++) {
            const int c = tn0 + nt * 8 + 2 * (lane & 3);
#pragma unroll
            for (int half = 0; half < 2; half++) {
                const int m = tm0 + mt * 16 + (lane >> 2) + half * 8;
                const float e0 = __expf(acc[mt][nt][half * 2]);
                const float e1 = __expf(acc[mt][nt][half * 2 + 1]);
                *reinterpret_cast<unsigned*>(Pp + (size_t)m * S_ + c) = pack_h2(e0, e1);
                rpart[mt][half] += e0 + e1;
            }
        }

    const int slot = blockIdx.x * 2 + wn;
#pragma unroll
    for (int mt = 0; mt < 2; mt++)
#pragma unroll
        for (int half = 0; half < 2; half++) {
            float v = rpart[mt][half];
            v += __shfl_xor_sync(0xffffffffu, v, 1);
            v += __shfl_xor_sync(0xffffffffu, v, 2);
            if ((lane & 3) == 0) {
                const int m = tm0 + mt * 16 + (lane >> 2) + half * 8;
                g_rsum_part[slot][(size_t)bh * S_ + m] = v;
            }
        }
}

// ---------------- inv_kernel: 1/rowsum from 64 partials ------------------------
__global__ void inv_kernel()
{
    const int r = blockIdx.x * 256 + threadIdx.x;   // 65536 rows
    float s = 0.f;
#pragma unroll
    for (int p = 0; p < 64; p++) s += g_rsum_part[p][r];
    g_inv[r] = 1.0f / s;
}

// =============================================================================
// Kernel 3: pv split-K=4: partial ctx = (P·V)·inv ; writes normalized attn fp32
// =============================================================================
__global__ __launch_bounds__(256, 2) void pv_gemm(float* __restrict__ attn_arg)
{
    extern __shared__ char sm[];
    __shared__ float s_inv[128];
    const unsigned sb = smem_u32(sm);
    float* attn = attn_arg ? attn_arg : g_attn_fb;
    const int kz = blockIdx.x, bh = blockIdx.z;
    const int m0 = blockIdx.y * 128;
    const int tid = threadIdx.x, lane = tid & 31, wid = tid >> 5;
    const int wm = wid >> 1, wn = wid & 1;

    if (tid < 128) s_inv[tid] = g_inv[(size_t)bh * S_ + m0 + tid];

    const __half* Pp = g_p1 + (size_t)bh * S_ * S_;
    const __half* Vp = g_vt + (size_t)bh * DK_ * S_;
    float* Aout = attn + (size_t)bh * S_ * S_;

    float acc[2][4][4] = {};
    const int kbase = kz * 512;

    cpA1_tile(sb + OFF1_A, Pp, S_, m0, kbase, tid);
    cpB1_tile(sb + OFF1_B, Vp, S_, 0, kbase, tid);
    CP_COMMIT;
    for (int it = 0; it < 8; it++) {
        const int cur = it & 1;
        const unsigned cb = sb + cur * STAGE1_BYTES;
        const int k0 = kbase + it * 64;
        if (it + 1 < 8) {
            const unsigned nb = sb + (1 - cur) * STAGE1_BYTES;
            cpA1_tile(nb + OFF1_A, Pp, S_, m0, k0 + 64, tid);
            cpB1_tile(nb + OFF1_B, Vp, S_, 0, k0 + 64, tid);
            CP_COMMIT;
            CP_WAIT1;
        } else { CP_WAIT0; }
        __syncthreads();

        // write normalized attn fp32 from this stage's A tile (each elem once)
        const char* cbc = sm + cur * STAGE1_BYTES;
#pragma unroll
        for (int j = 0; j < 4; j++) {
            int id = tid + j * 256, row = id >> 3, c = id & 7;
            uint4 pv4 = *reinterpret_cast<const uint4*>(cbc + OFF1_A + swz(row, c * 16));
            const float inv = s_inv[row];
            float4 o0, o1;
            float2 f;
            f = __half22float2(*reinterpret_cast<__half2*>(&pv4.x));
            o0.x = f.x * inv;  o0.y = f.y * inv;
            f = __half22float2(*reinterpret_cast<__half2*>(&pv4.y));
            o0.z = f.x * inv;  o0.w = f.y * inv;
            f = __half22float2(*reinterpret_cast<__half2*>(&pv4.z));
            o1.x = f.x * inv;  o1.y = f.y * inv;
            f = __half22float2(*reinterpret_cast<__half2*>(&pv4.w));
            o1.z = f.x * inv;  o1.w = f.y * inv;
            float* dst = Aout + (size_t)(m0 + row) * S_ + k0 + c * 8;
            *reinterpret_cast<float4*>(dst)     = o0;
            *reinterpret_cast<float4*>(dst + 4) = o1;
        }

        compute_stage1(cb + OFF1_A, cb + OFF1_B, wm, wn, lane, acc);
        __syncthreads();
    }

    // epilogue: fp32 partial ctx scaled by inv
    const int b = bh >> 4, h = bh & 15;
    float* dst = g_ctxp + (size_t)kz * BS_ * D_;
#pragma unroll
    for (int mt = 0; mt < 2; mt++)
#pragma unroll
        for (int nt = 0; nt < 4; nt++) {
            const int c = wn * 32 + nt * 8 + 2 * (lane & 3);
#pragma unroll
            for (int half = 0; half < 2; half++) {
                const int rowl = wm * 32 + mt * 16 + (lane >> 2) + half * 8;
                const float inv = s_inv[rowl];
                const int s = m0 + rowl;
                float2 v = { acc[mt][nt][half * 2] * inv,
                             acc[mt][nt][half * 2 + 1] * inv };
                *reinterpret_cast<float2*>(&dst[(size_t)(b * S_ + s) * D_ + h * DK_ + c]) = v;
            }
        }
}

// ---------------- ctx reduce: sum 4 partials -> single fp16 --------------------
__global__ void ctx_reduce()
{
    const size_t i = ((size_t)blockIdx.x * 256 + threadIdx.x) * 2;
    float2 s = {0.f, 0.f};
#pragma unroll
    for (int p = 0; p < 4; p++) {
        float2 v = *reinterpret_cast<const float2*>(&g_ctxp[(size_t)p * BS_ * D_ + i]);
        s.x += v.x; s.y += v.y;
    }
    *reinterpret_cast<unsigned*>(g_c1 + i) = pack_h2(s.x, s.y);
}

// =============================================================================
// Kernel 4: out = ctx @ Wo^T + bo (A single)
// =============================================================================
__global__ __launch_bounds__(256, 2) void oproj_gemm(const float* __restrict__ bo,
                                                     float* __restrict__ out)
{
    extern __shared__ char sm[];
    const unsigned sb = smem_u32(sm);
    const int m0 = blockIdx.y * 128, n0 = blockIdx.x * 64;
    const int tid = threadIdx.x, lane = tid & 31, wid = tid >> 5;
    const int wm = wid >> 1, wn = wid & 1;
    float acc[2][4][4] = {};

    cpA1_tile(sb + OFF1_A, g_c1, D_, m0, 0, tid);
    cpB1_tile(sb + OFF1_B, g_wo, D_, n0, 0, tid);
    CP_COMMIT;
    for (int it = 0; it < 16; it++) {
        const unsigned cb = sb + (it & 1) * STAGE1_BYTES;
        if (it + 1 < 16) {
            const unsigned nb = sb + ((it + 1) & 1) * STAGE1_BYTES;
            cpA1_tile(nb + OFF1_A, g_c1, D_, m0, (it + 1) * 64, tid);
            cpB1_tile(nb + OFF1_B, g_wo, D_, n0, (it + 1) * 64, tid);
            CP_COMMIT;
            CP_WAIT1;
        } else { CP_WAIT0; }
        __syncthreads();
        compute_stage1(cb + OFF1_A, cb + OFF1_B, wm, wn, lane, acc);
        __syncthreads();
    }

    const int tm0 = m0 + wm * 32, tn0 = n0 + wn * 32;
#pragma unroll
    for (int mt = 0; mt < 2; mt++)
#pragma unroll
        for (int nt = 0; nt < 4; nt++) {
            const int c = tn0 + nt * 8 + 2 * (lane & 3);
            const float b0 = bo[c], b1 = bo[c + 1];
#pragma unroll
            for (int half = 0; half < 2; half++) {
                const int m = tm0 + mt * 16 + (lane >> 2) + half * 8;
                float2 v = { acc[mt][nt][half * 2] + b0,
                             acc[mt][nt][half * 2 + 1] + b1 };
                *reinterpret_cast<float2*>(out + (size_t)m * D_ + c) = v;
            }
        }
}

// =============================================================================
extern "C" void kernel_launch(void* const* d_in, const int* in_sizes, int n_in,
                              void* d_out, int out_size)
{
    const float* x  = (const float*)d_in[0];
    const float* wq = (const float*)d_in[1];
    const float* bq = (const float*)d_in[2];
    const float* wk = (const float*)d_in[3];
    const float* bk = (const float*)d_in[4];
    const float* wv = (const float*)d_in[5];
    const float* bv = (const float*)d_in[6];
    const float* wo = (const float*)d_in[7];
    const float* bo = (const float*)d_in[8];

    float* out = (float*)d_out;
    const long long OUT_E  = (long long)BS_ * D_;
    const long long ATTN_E = (long long)NBH_ * S_ * S_;
    float* attn = ((long long)out_size >= OUT_E + ATTN_E) ? (out + OUT_E) : nullptr;

    static bool attr_done = false;
    if (!attr_done) {
        cudaFuncSetAttribute(qkv_gemm,    cudaFuncAttributeMaxDynamicSharedMemorySize, 2 * STAGE1_BYTES);
        cudaFuncSetAttribute(pv_gemm,     cudaFuncAttributeMaxDynamicSharedMemorySize, 2 * STAGE1_BYTES);
        cudaFuncSetAttribute(oproj_gemm,  cudaFuncAttributeMaxDynamicSharedMemorySize, 2 * STAGE1_BYTES);
        cudaFuncSetAttribute(scores_gemm, cudaFuncAttributeMaxDynamicSharedMemorySize, STAGE1_BYTES);
        attr_done = true;
    }

    // 0. precision casts
    prep_kernel<<<16384, 256>>>(x, wq, wk, wv, wo);

    // 1. QKV projection (single-A), Q pre-scaled by 1/8
    qkv_gemm<<<dim3(3 * D_ / 64, BS_ / 128), 256, 2 * STAGE1_BYTES>>>(bq, bk, bv);

    // 2. P = exp(QK^T/8) single fp16 + deterministic partial row sums (single-A)
    scores_gemm<<<dim3(S_ / 64, S_ / 128, NBH_), 256, STAGE1_BYTES>>>();

    // 3. inverse row sums
    inv_kernel<<<NBH_ * S_ / 256, 256>>>();

    // 4. pv split-K=4: partial ctx + normalized attn fp32 output
    pv_gemm<<<dim3(4, S_ / 128, NBH_), 256, 2 * STAGE1_BYTES>>>(attn);

    // 5. reduce ctx partials -> single fp16
    ctx_reduce<<<BS_ * D_ / 512, 256>>>();

    // 6. out projection
    oproj_gemm<<<dim3(D_ / 64, BS_ / 128), 256, 2 * STAGE1_BYTES>>>(bo, out);
}